// round 14
// baseline (speedup 1.0000x reference)
#include <cuda_runtime.h>
#include <math.h>

#define NN 100000
#define NE 3200000
#define SLOPE 0.01f

// ---------------- scratch (device globals; no allocation allowed) ----------
__device__ __align__(16) int   g_cnt   [NN];
__device__ __align__(16) int   g_rowptr[NN + 1];
__device__ __align__(16) int   g_next  [NN];
__device__ __align__(16) int   g_bsum  [32];
__device__ __align__(16) int   g_csr   [NE];
__device__ __align__(16) float g_dinv  [NN];
__device__ __align__(16) float g_h     [NN*16];   // xw1 after gather0
__device__ __align__(16) float g_xw    [NN*16];   // UNSCALED xw0 after k_pre
__device__ float g_W[2*256];
__device__ int   g_is64;

__device__ __forceinline__ float lrelu(float v){ return v > 0.f ? v : SLOPE*v; }
__device__ __forceinline__ int   clampi(int v){ return v < 0 ? 0 : (v >= NN ? NN-1 : v); }

// packed fp32x2 helpers (Blackwell)
__device__ __forceinline__ unsigned long long pk2(float a, float b){
    unsigned long long r;
    asm("mov.b64 %0, {%1, %2};" : "=l"(r) : "f"(a), "f"(b));
    return r;
}
__device__ __forceinline__ unsigned long long fma2(unsigned long long a,
                                                   unsigned long long b,
                                                   unsigned long long c){
    unsigned long long d;
    asm("fma.rn.f32x2 %0, %1, %2, %3;" : "=l"(d) : "l"(a), "l"(b), "l"(c));
    return d;
}
__device__ __forceinline__ float2 upk2(unsigned long long v){
    float2 r;
    asm("mov.b64 {%0, %1}, %2;" : "=f"(r.x), "=f"(r.y) : "l"(v));
    return r;
}

// ---------------- fused init: block0=dtype detect, block1=hyper, rest=cnt0 ----
__global__ void __launch_bounds__(512)
k_init(const int* __restrict__ ei32,
       const float* __restrict__ bih, const float* __restrict__ bhh,
       const float* __restrict__ wtW, const float* __restrict__ wtb){
    int b = blockIdx.x;
    if (b == 0){
        __shared__ int any;
        if (threadIdx.x == 0) any = 0;
        __syncthreads();
        int v = 0;
#pragma unroll
        for (int q = 0; q < 6; q++){
            int e = threadIdx.x + 512*q;
            v |= ei32[2*e + 1];
        }
        if (v) atomicOr(&any, 1);
        __syncthreads();
        if (threadIdx.x == 0) g_is64 = (any == 0) ? 1 : 0;
    } else if (b == 1){
        int t = threadIdx.x;
        int l = t >> 8, j = t & 255;
        float mem[16];
#pragma unroll
        for (int m = 0; m < 16; m++){
            float r = 1.f/(1.f + expf(-(bih[l*48 + m]      + bhh[l*48 + m])));
            float z = 1.f/(1.f + expf(-(bih[l*48 + 16 + m] + bhh[l*48 + 16 + m])));
            float n = tanhf(bih[l*48 + 32 + m] + r*bhh[l*48 + 32 + m]);
            mem[m] = (1.f - z) * n;
        }
        float acc = wtb[l*256 + j];
#pragma unroll
        for (int m = 0; m < 16; m++) acc += wtW[(l*256 + j)*16 + m] * mem[m];
        g_W[l*256 + j] = acc;
    } else {
        int i = (b - 2)*512 + threadIdx.x;
        if (i < NN) g_cnt[i] = 0;
    }
}

// ---------------- degree count (dst row only); low-reg for co-residency --------
__global__ void __launch_bounds__(256) k_edges(const int* __restrict__ ei32){
    int p = blockIdx.x*blockDim.x + threadIdx.x;
    if (p >= NE/2) return;
    int d0, d1;
    if (g_is64){
        const longlong2* v = (const longlong2*)ei32;
        longlong2 dv = v[(NE >> 1) + p];
        d0 = (int)dv.x; d1 = (int)dv.y;
    } else {
        const int2* v = (const int2*)ei32;
        int2 dv = v[(NE >> 1) + p];
        d0 = dv.x; d1 = dv.y;
    }
    atomicAdd(&g_cnt[clampi(d0)], 1);
    atomicAdd(&g_cnt[clampi(d1)], 1);
}

// ---------------- exclusive scan (+dinv); 256 thr x 16 items, low-reg -----------
__global__ void __launch_bounds__(256) k_scan1(){
    __shared__ int ts[256];
    int b = blockIdx.x, t = threadIdx.x;
    int base = b*4096 + t*16;
    int v[16]; int s = 0;
#pragma unroll
    for (int k = 0; k < 16; k++){
        int idx = base + k;
        v[k] = (idx < NN) ? g_cnt[idx] : 0;
        s += v[k];
        if (idx < NN) g_dinv[idx] = rsqrtf((float)v[k] + 1.0f);
    }
    ts[t] = s; __syncthreads();
#pragma unroll
    for (int off = 1; off < 256; off <<= 1){
        int y = (t >= off) ? ts[t - off] : 0;
        __syncthreads();
        ts[t] += y;
        __syncthreads();
    }
    if (t == 255) g_bsum[b] = ts[255];
    int run = ts[t] - s;
#pragma unroll
    for (int k = 0; k < 16; k++){
        if (base + k < NN) g_rowptr[base + k] = run;
        run += v[k];
    }
}
// scan3 with inline scan2
__global__ void __launch_bounds__(256) k_scan3(){
    __shared__ int bs[32];
    if (threadIdx.x == 0){
        int run = 0;
        for (int j = 0; j < 25; j++){ bs[j] = run; run += g_bsum[j]; }
    }
    __syncthreads();
    int i = blockIdx.x*blockDim.x + threadIdx.x;
    if (i < NN){
        int r = g_rowptr[i] + bs[i >> 12];
        g_rowptr[i] = r;
        g_next[i]   = r;
    }
    if (i == 0) g_rowptr[NN] = NE;
}

// ---------------- CSR fill --------------------------------------------------------
__global__ void __launch_bounds__(256) k_fill(const int* __restrict__ ei32){
    int e = blockIdx.x*blockDim.x + threadIdx.x;
    if (e >= NE) return;
    int s, d;
    if (g_is64){
        s = ei32[2*(size_t)e];
        d = ei32[2*((size_t)NE + e)];
    } else {
        s = ei32[e];
        d = ei32[NE + e];
    }
    s = clampi(s); d = clampi(d);
    int pos = atomicAdd(&g_next[d], 1);
    if (pos >= 0 && pos < NE) g_csr[pos] = s;
}

// ---------------- fused preprocess MLP + unscaled xw0 ------------------------------
// 5 independent 128-thread groups per block (20 warps/SM), 8 nodes per group-iter.
// 2 named barriers/iter; warp-shuffle epilogue. Reg-capped for CSR co-residency.
#define P_W1  0         // 32768: blocked w1v[j*256+r] = W1[r][4j..4j+3]
#define P_W2  32768     // 4352 = 256*17 padded transpose
#define P_B2  37120     // 16
#define P_W0  37136     // 256 transposed: W0t[i*16+o] = W0[o][i]
#define P_XG  37392     // 5120: 5 groups x (4 pairs x 128 k x float2)
#define P_H1G 42512     // 10240: 5 groups x (4 pairs x 256 o x float2)
#define P_RG  52752     // 5120: 5 groups x (4 pairs x 8 part x 16 o x float2)
#define PRE_SMEM_FLOATS 57872
#define PRE_SMEM_BYTES  (PRE_SMEM_FLOATS*4)   // 231488 <= 232448

#define GBAR() asm volatile("bar.sync %0, %1;" :: "r"(1 + wg), "r"(128) : "memory")

__global__ void __launch_bounds__(640, 1)
k_pre(const float* __restrict__ x,
      const float* __restrict__ p1W, const float* __restrict__ p1b,
      const float* __restrict__ p2W, const float* __restrict__ p2b){
    extern __shared__ float sm[];
    int t  = threadIdx.x;
    int wg = t >> 7;        // group 0..4
    int wt = t & 127;

    {
        float4* w1v = (float4*)(sm + P_W1);
        const float4* p1W4 = (const float4*)p1W;
        for (int i = t; i < 8192; i += 640){
            int j = i >> 8, r = i & 255;
            w1v[i] = p1W4[r*32 + j];
        }
        for (int i = t; i < 4096; i += 640){
            int k = i >> 4, o = i & 15;
            sm[P_W2 + k*17 + o] = p2W[o*256 + k];
        }
        if (t < 16) sm[P_B2 + t] = p2b[t];
        if (t < 256) sm[P_W0 + t] = g_W[(t & 15)*16 + (t >> 4)];
    }

    const int first  = (blockIdx.x*5 + wg)*8;
    const int stride = gridDim.x*40;

    float*  Xg  = sm + P_XG + wg*1024;
    float2* Xw  = (float2*)Xg;
    const ulonglong2* xq = (const ulonglong2*)Xg;
    float2* hbp = (float2*)(sm + P_H1G + wg*2048);
    const unsigned long long* hbu = (const unsigned long long*)(sm + P_H1G + wg*2048);
    unsigned long long* sru = (unsigned long long*)(sm + P_RG + wg*1024);
    const float2* srp = (const float2*)(sm + P_RG + wg*1024);

    if (first < NN){
#pragma unroll
        for (int r = 0; r < 4; r++){
            int e = wt + 128*r, p = e >> 7, k = e & 127;
            Xw[p*128 + k] = make_float2(x[(size_t)(first + 2*p    )*128 + k],
                                        x[(size_t)(first + 2*p + 1)*128 + k]);
        }
    }
    __syncthreads();

    float b0 = p1b[wt], b1 = p1b[128 + wt];

    for (int base = first; base < NN; base += stride){
        int nbase = base + stride;
        bool hasnext = (nbase < NN);

        float2 nx0, nx1, nx2, nx3;
        if (hasnext){
            nx0 = make_float2(x[(size_t)(nbase    )*128 + wt], x[(size_t)(nbase + 1)*128 + wt]);
            nx1 = make_float2(x[(size_t)(nbase + 2)*128 + wt], x[(size_t)(nbase + 3)*128 + wt]);
            nx2 = make_float2(x[(size_t)(nbase + 4)*128 + wt], x[(size_t)(nbase + 5)*128 + wt]);
            nx3 = make_float2(x[(size_t)(nbase + 6)*128 + wt], x[(size_t)(nbase + 7)*128 + wt]);
        }

        unsigned long long a00, a01, a02, a03, a10, a11, a12, a13;
        a00 = a01 = a02 = a03 = pk2(b0, b0);
        a10 = a11 = a12 = a13 = pk2(b1, b1);
        const float4* wv = (const float4*)(sm + P_W1);
#pragma unroll 2
        for (int j = 0; j < 32; j++){
            float4 wA = wv[j*256 + wt];
            float4 wB = wv[j*256 + 128 + wt];
            ulonglong2 x0a = xq[0*64 + 2*j], x0b = xq[0*64 + 2*j + 1];
            ulonglong2 x1a = xq[1*64 + 2*j], x1b = xq[1*64 + 2*j + 1];
            ulonglong2 x2a = xq[2*64 + 2*j], x2b = xq[2*64 + 2*j + 1];
            ulonglong2 x3a = xq[3*64 + 2*j], x3b = xq[3*64 + 2*j + 1];
            unsigned long long wA0 = pk2(wA.x, wA.x), wA1 = pk2(wA.y, wA.y);
            unsigned long long wA2 = pk2(wA.z, wA.z), wA3 = pk2(wA.w, wA.w);
            a00 = fma2(wA0, x0a.x, a00); a00 = fma2(wA1, x0a.y, a00);
            a00 = fma2(wA2, x0b.x, a00); a00 = fma2(wA3, x0b.y, a00);
            a01 = fma2(wA0, x1a.x, a01); a01 = fma2(wA1, x1a.y, a01);
            a01 = fma2(wA2, x1b.x, a01); a01 = fma2(wA3, x1b.y, a01);
            a02 = fma2(wA0, x2a.x, a02); a02 = fma2(wA1, x2a.y, a02);
            a02 = fma2(wA2, x2b.x, a02); a02 = fma2(wA3, x2b.y, a02);
            a03 = fma2(wA0, x3a.x, a03); a03 = fma2(wA1, x3a.y, a03);
            a03 = fma2(wA2, x3b.x, a03); a03 = fma2(wA3, x3b.y, a03);
            unsigned long long wB0 = pk2(wB.x, wB.x), wB1 = pk2(wB.y, wB.y);
            unsigned long long wB2 = pk2(wB.z, wB.z), wB3 = pk2(wB.w, wB.w);
            a10 = fma2(wB0, x0a.x, a10); a10 = fma2(wB1, x0a.y, a10);
            a10 = fma2(wB2, x0b.x, a10); a10 = fma2(wB3, x0b.y, a10);
            a11 = fma2(wB0, x1a.x, a11); a11 = fma2(wB1, x1a.y, a11);
            a11 = fma2(wB2, x1b.x, a11); a11 = fma2(wB3, x1b.y, a11);
            a12 = fma2(wB0, x2a.x, a12); a12 = fma2(wB1, x2a.y, a12);
            a12 = fma2(wB2, x2b.x, a12); a12 = fma2(wB3, x2b.y, a12);
            a13 = fma2(wB0, x3a.x, a13); a13 = fma2(wB1, x3a.y, a13);
            a13 = fma2(wB2, x3b.x, a13); a13 = fma2(wB3, x3b.y, a13);
        }
        {
            float2 y;
            y = upk2(a00); hbp[0*256 + wt]       = make_float2(lrelu(y.x), lrelu(y.y));
            y = upk2(a01); hbp[1*256 + wt]       = make_float2(lrelu(y.x), lrelu(y.y));
            y = upk2(a02); hbp[2*256 + wt]       = make_float2(lrelu(y.x), lrelu(y.y));
            y = upk2(a03); hbp[3*256 + wt]       = make_float2(lrelu(y.x), lrelu(y.y));
            y = upk2(a10); hbp[0*256 + 128 + wt] = make_float2(lrelu(y.x), lrelu(y.y));
            y = upk2(a11); hbp[1*256 + 128 + wt] = make_float2(lrelu(y.x), lrelu(y.y));
            y = upk2(a12); hbp[2*256 + 128 + wt] = make_float2(lrelu(y.x), lrelu(y.y));
            y = upk2(a13); hbp[3*256 + 128 + wt] = make_float2(lrelu(y.x), lrelu(y.y));
        }
        GBAR();   // h1 visible; X consumed

        if (hasnext){
            Xw[0*128 + wt] = nx0;
            Xw[1*128 + wt] = nx1;
            Xw[2*128 + wt] = nx2;
            Xw[3*128 + wt] = nx3;
        }
        {
            int o = wt & 15, part = wt >> 4;
            unsigned long long c0 = 0ULL, c1 = 0ULL, c2 = 0ULL, c3 = 0ULL;
#pragma unroll
            for (int kk = 0; kk < 32; kk++){
                int k = part*32 + kk;
                float w2s = sm[P_W2 + k*17 + o];
                unsigned long long w2 = pk2(w2s, w2s);
                c0 = fma2(w2, hbu[0*256 + k], c0);
                c1 = fma2(w2, hbu[1*256 + k], c1);
                c2 = fma2(w2, hbu[2*256 + k], c2);
                c3 = fma2(w2, hbu[3*256 + k], c3);
            }
            sru[0*128 + part*16 + o] = c0;
            sru[1*128 + part*16 + o] = c1;
            sru[2*128 + part*16 + o] = c2;
            sru[3*128 + part*16 + o] = c3;
        }
        GBAR();   // partials visible; X stable for next iter

        // merged epilogue: final h + unscaled xw0 via warp shuffles (warps 0-1)
        if (wt < 64){
            int p = wt >> 4, o = wt & 15;
            float sx = 0.f, sy = 0.f;
#pragma unroll
            for (int q = 0; q < 8; q++){
                float2 v = srp[p*128 + q*16 + o];
                sx += v.x; sy += v.y;
            }
            float bb2 = sm[P_B2 + o];
            sx += bb2; sy += bb2;
            sx = fmaxf(sx, SLOPE*sx);
            sy = fmaxf(sy, SLOPE*sy);
            float ax = 0.f, ay = 0.f;
            int sb = (p & 1) << 4;
#pragma unroll
            for (int i = 0; i < 16; i++){
                float hx = __shfl_sync(0xffffffffu, sx, sb + i);
                float hy = __shfl_sync(0xffffffffu, sy, sb + i);
                float w = sm[P_W0 + i*16 + o];
                ax = fmaf(hx, w, ax);
                ay = fmaf(hy, w, ay);
            }
            int n0 = base + 2*p;
            g_xw[(size_t)n0*16 + o]       = ax;
            g_xw[(size_t)(n0 + 1)*16 + o] = ay;
        }
        // no barrier: sru rewritten only after next iter's GBAR(1).
    }
}

// ---------------- gather layer 0 (dinv folded per edge) + fused xw1 -----------------
__global__ void __launch_bounds__(256)
k_gather0(const float* __restrict__ gcnb){
    __shared__ float Ws[256];   // W1 (gcn layer1) transposed
    Ws[threadIdx.x] = g_W[256 + (threadIdx.x & 15)*16 + (threadIdx.x >> 4)];
    __syncthreads();

    int warp = (blockIdx.x*blockDim.x + threadIdx.x) >> 5;
    int lane = threadIdx.x & 31;
    if (warp >= NN) return;
    int node = warp;
    int slot = lane >> 2;
    int cg   = lane & 3;
    int beg = g_rowptr[node], end = g_rowptr[node + 1];
    const float4* xw4 = (const float4*)g_xw;
    float di = g_dinv[node];

    float4 acc;
    if (slot == 0){
        float4 v = xw4[(size_t)node*4 + cg];
        acc = make_float4(v.x*di, v.y*di, v.z*di, v.w*di);
    } else {
        acc = make_float4(0.f, 0.f, 0.f, 0.f);
    }

    for (int j = beg + slot; j < end; j += 8){
        int s = g_csr[j];
        float ds = g_dinv[s];
        float4 v = xw4[(size_t)s*4 + cg];
        acc.x = fmaf(v.x, ds, acc.x);
        acc.y = fmaf(v.y, ds, acc.y);
        acc.z = fmaf(v.z, ds, acc.z);
        acc.w = fmaf(v.w, ds, acc.w);
    }
#pragma unroll
    for (int off = 4; off < 32; off <<= 1){
        acc.x += __shfl_xor_sync(0xffffffff, acc.x, off);
        acc.y += __shfl_xor_sync(0xffffffff, acc.y, off);
        acc.z += __shfl_xor_sync(0xffffffff, acc.z, off);
        acc.w += __shfl_xor_sync(0xffffffff, acc.w, off);
    }
    const float* bp = gcnb + cg*4;
    float4 r;
    r.x = lrelu(di*acc.x + bp[0]);
    r.y = lrelu(di*acc.y + bp[1]);
    r.z = lrelu(di*acc.z + bp[2]);
    r.w = lrelu(di*acc.w + bp[3]);

    float hv[16];
    int qb = lane & ~3;
#pragma unroll
    for (int c = 0; c < 4; c++){
        int src = qb + c;
        hv[c*4+0] = __shfl_sync(0xffffffff, r.x, src);
        hv[c*4+1] = __shfl_sync(0xffffffff, r.y, src);
        hv[c*4+2] = __shfl_sync(0xffffffff, r.z, src);
        hv[c*4+3] = __shfl_sync(0xffffffff, r.w, src);
    }
    if (lane < 16){
        float a = 0.f;
#pragma unroll
        for (int i = 0; i < 16; i++) a += hv[i]*Ws[i*16 + lane];
        g_h[(size_t)node*16 + lane] = a * di;
    }
}

// ---------------- gather layer 1 + fused post heads ---------------------------------
__global__ void __launch_bounds__(256)
k_gather2(const float* __restrict__ gcnb,
          const float* __restrict__ po1W, const float* __restrict__ po1b,
          const float* __restrict__ poaW, const float* __restrict__ poab,
          float* __restrict__ out, int out_size){
    int warp = (blockIdx.x*blockDim.x + threadIdx.x) >> 5;
    int lane = threadIdx.x & 31;
    if (warp >= NN) return;
    int node = warp;
    int slot = lane >> 2;
    int cg   = lane & 3;
    int beg = g_rowptr[node], end = g_rowptr[node + 1];
    const float4* xw4 = (const float4*)g_h;

    float4 acc;
    if (slot == 0) acc = xw4[(size_t)node*4 + cg];
    else           acc = make_float4(0.f, 0.f, 0.f, 0.f);

    for (int j = beg + slot; j < end; j += 8){
        int s = g_csr[j];
        float4 v = xw4[(size_t)s*4 + cg];
        acc.x += v.x; acc.y += v.y; acc.z += v.z; acc.w += v.w;
    }
#pragma unroll
    for (int off = 4; off < 32; off <<= 1){
        acc.x += __shfl_xor_sync(0xffffffff, acc.x, off);
        acc.y += __shfl_xor_sync(0xffffffff, acc.y, off);
        acc.z += __shfl_xor_sync(0xffffffff, acc.z, off);
        acc.w += __shfl_xor_sync(0xffffffff, acc.w, off);
    }
    if (lane < 4){
        float di = g_dinv[node];
        const float* bp = gcnb + 16 + cg*4;
        float4 r;
        r.x = lrelu(di*acc.x + bp[0]);
        r.y = lrelu(di*acc.y + bp[1]);
        r.z = lrelu(di*acc.z + bp[2]);
        r.w = lrelu(di*acc.w + bp[3]);
        if (out_size >= 18*NN)
            ((float4*)(out + 2*NN))[(size_t)node*4 + cg] = r;
        int c0 = cg*4;
        float sp = r.x*(po1W[c0+0] + po1W[16+c0+0])
                 + r.y*(po1W[c0+1] + po1W[16+c0+1])
                 + r.z*(po1W[c0+2] + po1W[16+c0+2])
                 + r.w*(po1W[c0+3] + po1W[16+c0+3]);
        float ap = r.x*poaW[c0+0] + r.y*poaW[c0+1]
                 + r.z*poaW[c0+2] + r.w*poaW[c0+3];
        unsigned qm = 0xFu << ((lane >> 2) << 2);
        sp += __shfl_xor_sync(qm, sp, 1); sp += __shfl_xor_sync(qm, sp, 2);
        ap += __shfl_xor_sync(qm, ap, 1); ap += __shfl_xor_sync(qm, ap, 2);
        if (cg == 0){
            out[node] = sp + po1b[0] + po1b[1];
            if (out_size >= 2*NN) out[NN + node] = ap + poab[0];
        }
    }
}

// ---------------- launch --------------------------------------------------------------
extern "C" void kernel_launch(void* const* d_in, const int* in_sizes, int n_in,
                              void* d_out, int out_size){
    const float* x    = (const float*)d_in[0];
    const int*   ei32 = (const int*)d_in[1];
    const float* p1W  = (const float*)d_in[2];
    const float* p1b  = (const float*)d_in[3];
    const float* p2W  = (const float*)d_in[4];
    const float* p2b  = (const float*)d_in[5];
    const float* bih  = (const float*)d_in[6];
    const float* bhh  = (const float*)d_in[7];
    const float* wtW  = (const float*)d_in[8];
    const float* wtb  = (const float*)d_in[9];
    const float* gcnb = (const float*)d_in[10];
    const float* po1W = (const float*)d_in[11];
    const float* po1b = (const float*)d_in[12];
    const float* poaW = (const float*)d_in[13];
    const float* poab = (const float*)d_in[14];
    float* out = (float*)d_out;

    cudaFuncSetAttribute(k_pre, cudaFuncAttributeMaxDynamicSharedMemorySize,
                         PRE_SMEM_BYTES);

    const int NB_N = (NN + 255)/256;
    const int NB_E = (NE + 255)/256;
    const int NB_E2 = (NE/2 + 255)/256;
    const int NB_SCAN = (NN + 4095)/4096;   // 25
    const int NB_G = (NN*32 + 255)/256;     // warp per node
    const int NB_I = 2 + (NN + 511)/512;

    cudaStream_t s2 = 0;
    cudaEvent_t  evA = 0, evB = 0;
    bool fork = (cudaStreamCreateWithFlags(&s2, cudaStreamNonBlocking) == cudaSuccess);
    if (fork) fork = (cudaEventCreateWithFlags(&evA, cudaEventDisableTiming) == cudaSuccess);
    if (fork) fork = (cudaEventCreateWithFlags(&evB, cudaEventDisableTiming) == cudaSuccess);

    k_init<<<NB_I, 512>>>(ei32, bih, bhh, wtW, wtb);

    if (fork){
        cudaEventRecord(evA, 0);
        cudaStreamWaitEvent(s2, evA, 0);
        k_edges<<<NB_E2, 256, 0, s2>>>(ei32);
        k_scan1<<<NB_SCAN, 256, 0, s2>>>();
        k_scan3<<<NB_N, 256, 0, s2>>>();
        k_fill <<<NB_E, 256, 0, s2>>>(ei32);
        cudaEventRecord(evB, s2);
        k_pre  <<<148, 640, PRE_SMEM_BYTES>>>(x, p1W, p1b, p2W, p2b);
        cudaStreamWaitEvent(0, evB, 0);
    } else {
        k_edges<<<NB_E2, 256>>>(ei32);
        k_scan1<<<NB_SCAN, 256>>>();
        k_scan3<<<NB_N, 256>>>();
        k_fill <<<NB_E, 256>>>(ei32);
        k_pre  <<<148, 640, PRE_SMEM_BYTES>>>(x, p1W, p1b, p2W, p2b);
    }

    k_gather0<<<NB_G, 256>>>(gcnb);
    k_gather2<<<NB_G, 256>>>(gcnb, po1W, po1b, poaW, poab, out, out_size);
}

// round 15
// speedup vs baseline: 1.0649x; 1.0649x over previous
#include <cuda_runtime.h>
#include <math.h>

#define NN 100000
#define NE 3200000
#define SLOPE 0.01f

// ---------------- scratch (device globals; no allocation allowed) ----------
__device__ __align__(16) int   g_cnt   [NN];
__device__ __align__(16) int   g_rowptr[NN + 1];
__device__ __align__(16) int   g_next  [NN];
__device__ __align__(16) int   g_bsum  [32];
__device__ __align__(16) int   g_csr   [NE];
__device__ __align__(16) float g_dinv  [NN];
__device__ __align__(16) float g_h     [NN*16];   // xw1 after gather0
__device__ __align__(16) float g_xw    [NN*16];   // UNSCALED xw0 after k_pre
__device__ float g_W[2*256];
__device__ int   g_is64;

__device__ __forceinline__ float lrelu(float v){ return v > 0.f ? v : SLOPE*v; }
__device__ __forceinline__ int   clampi(int v){ return v < 0 ? 0 : (v >= NN ? NN-1 : v); }

// packed fp32x2 helpers (Blackwell)
__device__ __forceinline__ unsigned long long pk2(float a, float b){
    unsigned long long r;
    asm("mov.b64 %0, {%1, %2};" : "=l"(r) : "f"(a), "f"(b));
    return r;
}
__device__ __forceinline__ unsigned long long fma2(unsigned long long a,
                                                   unsigned long long b,
                                                   unsigned long long c){
    unsigned long long d;
    asm("fma.rn.f32x2 %0, %1, %2, %3;" : "=l"(d) : "l"(a), "l"(b), "l"(c));
    return d;
}
__device__ __forceinline__ float2 upk2(unsigned long long v){
    float2 r;
    asm("mov.b64 {%0, %1}, %2;" : "=f"(r.x), "=f"(r.y) : "l"(v));
    return r;
}

// ---------------- fused init: block0=dtype detect, block1=hyper, rest=cnt0 ----
__global__ void __launch_bounds__(512)
k_init(const int* __restrict__ ei32,
       const float* __restrict__ bih, const float* __restrict__ bhh,
       const float* __restrict__ wtW, const float* __restrict__ wtb){
    int b = blockIdx.x;
    if (b == 0){
        __shared__ int any;
        if (threadIdx.x == 0) any = 0;
        __syncthreads();
        int v = 0;
#pragma unroll
        for (int q = 0; q < 6; q++){
            int e = threadIdx.x + 512*q;
            v |= ei32[2*e + 1];
        }
        if (v) atomicOr(&any, 1);
        __syncthreads();
        if (threadIdx.x == 0) g_is64 = (any == 0) ? 1 : 0;
    } else if (b == 1){
        int t = threadIdx.x;
        int l = t >> 8, j = t & 255;
        float mem[16];
#pragma unroll
        for (int m = 0; m < 16; m++){
            float r = 1.f/(1.f + expf(-(bih[l*48 + m]      + bhh[l*48 + m])));
            float z = 1.f/(1.f + expf(-(bih[l*48 + 16 + m] + bhh[l*48 + 16 + m])));
            float n = tanhf(bih[l*48 + 32 + m] + r*bhh[l*48 + 32 + m]);
            mem[m] = (1.f - z) * n;
        }
        float acc = wtb[l*256 + j];
#pragma unroll
        for (int m = 0; m < 16; m++) acc += wtW[(l*256 + j)*16 + m] * mem[m];
        g_W[l*256 + j] = acc;
    } else {
        int i = (b - 2)*512 + threadIdx.x;
        if (i < NN) g_cnt[i] = 0;
    }
}

// ---------------- degree count (dst row only); low-reg for co-residency --------
__global__ void __launch_bounds__(256) k_edges(const int* __restrict__ ei32){
    int p = blockIdx.x*blockDim.x + threadIdx.x;
    if (p >= NE/2) return;
    int d0, d1;
    if (g_is64){
        const longlong2* v = (const longlong2*)ei32;
        longlong2 dv = v[(NE >> 1) + p];
        d0 = (int)dv.x; d1 = (int)dv.y;
    } else {
        const int2* v = (const int2*)ei32;
        int2 dv = v[(NE >> 1) + p];
        d0 = dv.x; d1 = dv.y;
    }
    atomicAdd(&g_cnt[clampi(d0)], 1);
    atomicAdd(&g_cnt[clampi(d1)], 1);
}

// ---------------- exclusive scan (+dinv); 256 thr x 16 items, low-reg -----------
__global__ void __launch_bounds__(256) k_scan1(){
    __shared__ int ts[256];
    int b = blockIdx.x, t = threadIdx.x;
    int base = b*4096 + t*16;
    int v[16]; int s = 0;
#pragma unroll
    for (int k = 0; k < 16; k++){
        int idx = base + k;
        v[k] = (idx < NN) ? g_cnt[idx] : 0;
        s += v[k];
        if (idx < NN) g_dinv[idx] = rsqrtf((float)v[k] + 1.0f);
    }
    ts[t] = s; __syncthreads();
#pragma unroll
    for (int off = 1; off < 256; off <<= 1){
        int y = (t >= off) ? ts[t - off] : 0;
        __syncthreads();
        ts[t] += y;
        __syncthreads();
    }
    if (t == 255) g_bsum[b] = ts[255];
    int run = ts[t] - s;
#pragma unroll
    for (int k = 0; k < 16; k++){
        if (base + k < NN) g_rowptr[base + k] = run;
        run += v[k];
    }
}
// scan3 with inline scan2
__global__ void __launch_bounds__(256) k_scan3(){
    __shared__ int bs[32];
    if (threadIdx.x == 0){
        int run = 0;
        for (int j = 0; j < 25; j++){ bs[j] = run; run += g_bsum[j]; }
    }
    __syncthreads();
    int i = blockIdx.x*blockDim.x + threadIdx.x;
    if (i < NN){
        int r = g_rowptr[i] + bs[i >> 12];
        g_rowptr[i] = r;
        g_next[i]   = r;
    }
    if (i == 0) g_rowptr[NN] = NE;
}

// ---------------- CSR fill (2 edges/thread, 16B loads) -----------------------------
__global__ void __launch_bounds__(256) k_fill(const int* __restrict__ ei32){
    int p = blockIdx.x*blockDim.x + threadIdx.x;
    if (p >= NE/2) return;
    int s0, s1, d0, d1;
    if (g_is64){
        const longlong2* v = (const longlong2*)ei32;
        longlong2 sv = v[p];
        longlong2 dv = v[(NE >> 1) + p];
        s0 = (int)sv.x; s1 = (int)sv.y; d0 = (int)dv.x; d1 = (int)dv.y;
    } else {
        const int2* v = (const int2*)ei32;
        int2 sv = v[p];
        int2 dv = v[(NE >> 1) + p];
        s0 = sv.x; s1 = sv.y; d0 = dv.x; d1 = dv.y;
    }
    s0 = clampi(s0); s1 = clampi(s1); d0 = clampi(d0); d1 = clampi(d1);
    int p0 = atomicAdd(&g_next[d0], 1);
    int p1 = atomicAdd(&g_next[d1], 1);
    if (p0 >= 0 && p0 < NE) g_csr[p0] = s0;
    if (p1 >= 0 && p1 < NE) g_csr[p1] = s1;
}

// ---------------- fused preprocess MLP + unscaled xw0 ------------------------------
// 4 independent 128-thread groups per block, 8 nodes (4 pairs) per group-iter.
// 2 named barriers/iter; epilogue uses warp shuffles. Reg-capped (576 -> <=112).
#define P_W1  0         // 32768: blocked w1v[j*256+r] = W1[r][4j..4j+3]
#define P_W2  32768     // 4352 = 256*17 padded transpose
#define P_B2  37120     // 16
#define P_W0  37136     // 256 transposed: W0t[i*16+o] = W0[o][i]
#define P_XG  37392     // 4096: 4 groups x (4 pairs x 128 k x float2)
#define P_H1G 41488     // 8192: 4 groups x (4 pairs x 256 o x float2)
#define P_RG  49680     // 4096: 4 groups x (4 pairs x 8 part x 16 o x float2)
#define PRE_SMEM_FLOATS 53776
#define PRE_SMEM_BYTES  (PRE_SMEM_FLOATS*4)   // 215104

#define GBAR() asm volatile("bar.sync %0, %1;" :: "r"(1 + wg), "r"(128) : "memory")

__global__ void __launch_bounds__(576, 1)
k_pre(const float* __restrict__ x,
      const float* __restrict__ p1W, const float* __restrict__ p1b,
      const float* __restrict__ p2W, const float* __restrict__ p2b){
    extern __shared__ float sm[];
    int t  = threadIdx.x;
    int wg = t >> 7;
    int wt = t & 127;

    {
        float4* w1v = (float4*)(sm + P_W1);
        const float4* p1W4 = (const float4*)p1W;
        for (int i = t; i < 8192; i += 512){
            int j = i >> 8, r = i & 255;
            w1v[i] = p1W4[r*32 + j];
        }
        for (int i = t; i < 4096; i += 512){
            int k = i >> 4, o = i & 15;
            sm[P_W2 + k*17 + o] = p2W[o*256 + k];
        }
        if (t < 16) sm[P_B2 + t] = p2b[t];
        if (t < 256) sm[P_W0 + t] = g_W[(t & 15)*16 + (t >> 4)];
    }

    const int first  = (blockIdx.x*4 + wg)*8;
    const int stride = gridDim.x*32;

    float*  Xg  = sm + P_XG + wg*1024;
    float2* Xw  = (float2*)Xg;
    const ulonglong2* xq = (const ulonglong2*)Xg;
    float2* hbp = (float2*)(sm + P_H1G + wg*2048);
    const unsigned long long* hbu = (const unsigned long long*)(sm + P_H1G + wg*2048);
    unsigned long long* sru = (unsigned long long*)(sm + P_RG + wg*1024);
    const float2* srp = (const float2*)(sm + P_RG + wg*1024);

#pragma unroll
    for (int r = 0; r < 4; r++){
        int e = wt + 128*r, p = e >> 7, k = e & 127;
        Xw[p*128 + k] = make_float2(x[(size_t)(first + 2*p    )*128 + k],
                                    x[(size_t)(first + 2*p + 1)*128 + k]);
    }
    __syncthreads();

    float b0 = p1b[wt], b1 = p1b[128 + wt];

    for (int base = first; base < NN; base += stride){
        int nbase = base + stride;
        bool hasnext = (nbase < NN);

        float2 nx0, nx1, nx2, nx3;
        if (hasnext){
            nx0 = make_float2(x[(size_t)(nbase    )*128 + wt], x[(size_t)(nbase + 1)*128 + wt]);
            nx1 = make_float2(x[(size_t)(nbase + 2)*128 + wt], x[(size_t)(nbase + 3)*128 + wt]);
            nx2 = make_float2(x[(size_t)(nbase + 4)*128 + wt], x[(size_t)(nbase + 5)*128 + wt]);
            nx3 = make_float2(x[(size_t)(nbase + 6)*128 + wt], x[(size_t)(nbase + 7)*128 + wt]);
        }

        unsigned long long a00, a01, a02, a03, a10, a11, a12, a13;
        a00 = a01 = a02 = a03 = pk2(b0, b0);
        a10 = a11 = a12 = a13 = pk2(b1, b1);
        const float4* wv = (const float4*)(sm + P_W1);
#pragma unroll 2
        for (int j = 0; j < 32; j++){
            float4 wA = wv[j*256 + wt];
            float4 wB = wv[j*256 + 128 + wt];
            ulonglong2 x0a = xq[0*64 + 2*j], x0b = xq[0*64 + 2*j + 1];
            ulonglong2 x1a = xq[1*64 + 2*j], x1b = xq[1*64 + 2*j + 1];
            ulonglong2 x2a = xq[2*64 + 2*j], x2b = xq[2*64 + 2*j + 1];
            ulonglong2 x3a = xq[3*64 + 2*j], x3b = xq[3*64 + 2*j + 1];
            unsigned long long wA0 = pk2(wA.x, wA.x), wA1 = pk2(wA.y, wA.y);
            unsigned long long wA2 = pk2(wA.z, wA.z), wA3 = pk2(wA.w, wA.w);
            a00 = fma2(wA0, x0a.x, a00); a00 = fma2(wA1, x0a.y, a00);
            a00 = fma2(wA2, x0b.x, a00); a00 = fma2(wA3, x0b.y, a00);
            a01 = fma2(wA0, x1a.x, a01); a01 = fma2(wA1, x1a.y, a01);
            a01 = fma2(wA2, x1b.x, a01); a01 = fma2(wA3, x1b.y, a01);
            a02 = fma2(wA0, x2a.x, a02); a02 = fma2(wA1, x2a.y, a02);
            a02 = fma2(wA2, x2b.x, a02); a02 = fma2(wA3, x2b.y, a02);
            a03 = fma2(wA0, x3a.x, a03); a03 = fma2(wA1, x3a.y, a03);
            a03 = fma2(wA2, x3b.x, a03); a03 = fma2(wA3, x3b.y, a03);
            unsigned long long wB0 = pk2(wB.x, wB.x), wB1 = pk2(wB.y, wB.y);
            unsigned long long wB2 = pk2(wB.z, wB.z), wB3 = pk2(wB.w, wB.w);
            a10 = fma2(wB0, x0a.x, a10); a10 = fma2(wB1, x0a.y, a10);
            a10 = fma2(wB2, x0b.x, a10); a10 = fma2(wB3, x0b.y, a10);
            a11 = fma2(wB0, x1a.x, a11); a11 = fma2(wB1, x1a.y, a11);
            a11 = fma2(wB2, x1b.x, a11); a11 = fma2(wB3, x1b.y, a11);
            a12 = fma2(wB0, x2a.x, a12); a12 = fma2(wB1, x2a.y, a12);
            a12 = fma2(wB2, x2b.x, a12); a12 = fma2(wB3, x2b.y, a12);
            a13 = fma2(wB0, x3a.x, a13); a13 = fma2(wB1, x3a.y, a13);
            a13 = fma2(wB2, x3b.x, a13); a13 = fma2(wB3, x3b.y, a13);
        }
        {
            float2 y;
            y = upk2(a00); hbp[0*256 + wt]       = make_float2(lrelu(y.x), lrelu(y.y));
            y = upk2(a01); hbp[1*256 + wt]       = make_float2(lrelu(y.x), lrelu(y.y));
            y = upk2(a02); hbp[2*256 + wt]       = make_float2(lrelu(y.x), lrelu(y.y));
            y = upk2(a03); hbp[3*256 + wt]       = make_float2(lrelu(y.x), lrelu(y.y));
            y = upk2(a10); hbp[0*256 + 128 + wt] = make_float2(lrelu(y.x), lrelu(y.y));
            y = upk2(a11); hbp[1*256 + 128 + wt] = make_float2(lrelu(y.x), lrelu(y.y));
            y = upk2(a12); hbp[2*256 + 128 + wt] = make_float2(lrelu(y.x), lrelu(y.y));
            y = upk2(a13); hbp[3*256 + 128 + wt] = make_float2(lrelu(y.x), lrelu(y.y));
        }
        GBAR();   // h1 visible; X consumed

        if (hasnext){
            Xw[0*128 + wt] = nx0;
            Xw[1*128 + wt] = nx1;
            Xw[2*128 + wt] = nx2;
            Xw[3*128 + wt] = nx3;
        }
        {
            int o = wt & 15, part = wt >> 4;
            unsigned long long c0 = 0ULL, c1 = 0ULL, c2 = 0ULL, c3 = 0ULL;
#pragma unroll
            for (int kk = 0; kk < 32; kk++){
                int k = part*32 + kk;
                float w2s = sm[P_W2 + k*17 + o];
                unsigned long long w2 = pk2(w2s, w2s);
                c0 = fma2(w2, hbu[0*256 + k], c0);
                c1 = fma2(w2, hbu[1*256 + k], c1);
                c2 = fma2(w2, hbu[2*256 + k], c2);
                c3 = fma2(w2, hbu[3*256 + k], c3);
            }
            sru[0*128 + part*16 + o] = c0;
            sru[1*128 + part*16 + o] = c1;
            sru[2*128 + part*16 + o] = c2;
            sru[3*128 + part*16 + o] = c3;
        }
        GBAR();   // partials visible; X stable for next iter

        // merged epilogue: final h + unscaled xw0 via warp shuffles (warps 0-1)
        if (wt < 64){
            int p = wt >> 4, o = wt & 15;
            float sx = 0.f, sy = 0.f;
#pragma unroll
            for (int q = 0; q < 8; q++){
                float2 v = srp[p*128 + q*16 + o];
                sx += v.x; sy += v.y;
            }
            float bb2 = sm[P_B2 + o];
            sx += bb2; sy += bb2;
            sx = fmaxf(sx, SLOPE*sx);
            sy = fmaxf(sy, SLOPE*sy);
            float ax = 0.f, ay = 0.f;
            int sb = (p & 1) << 4;
#pragma unroll
            for (int i = 0; i < 16; i++){
                float hx = __shfl_sync(0xffffffffu, sx, sb + i);
                float hy = __shfl_sync(0xffffffffu, sy, sb + i);
                float w = sm[P_W0 + i*16 + o];
                ax = fmaf(hx, w, ax);
                ay = fmaf(hy, w, ay);
            }
            int n0 = base + 2*p;
            g_xw[(size_t)n0*16 + o]       = ax;
            g_xw[(size_t)(n0 + 1)*16 + o] = ay;
        }
        // no barrier: sru rewritten only after next iter's GBAR(1).
    }
}

// ---------------- gather layer 0 (dinv folded per edge) + fused xw1 -----------------
__global__ void __launch_bounds__(256)
k_gather0(const float* __restrict__ gcnb){
    __shared__ float Ws[256];   // W1 (gcn layer1) transposed
    Ws[threadIdx.x] = g_W[256 + (threadIdx.x & 15)*16 + (threadIdx.x >> 4)];
    __syncthreads();

    int warp = (blockIdx.x*blockDim.x + threadIdx.x) >> 5;
    int lane = threadIdx.x & 31;
    if (warp >= NN) return;
    int node = warp;
    int slot = lane >> 2;
    int cg   = lane & 3;
    int beg = g_rowptr[node], end = g_rowptr[node + 1];
    const float4* xw4 = (const float4*)g_xw;
    float di = g_dinv[node];

    float4 acc;
    if (slot == 0){
        float4 v = xw4[(size_t)node*4 + cg];
        acc = make_float4(v.x*di, v.y*di, v.z*di, v.w*di);
    } else {
        acc = make_float4(0.f, 0.f, 0.f, 0.f);
    }

    int j = beg + slot;
    for (; j + 8 < end; j += 16){
        int s0 = g_csr[j];
        int s1 = g_csr[j + 8];
        float ds0 = g_dinv[s0];
        float ds1 = g_dinv[s1];
        float4 v0 = xw4[(size_t)s0*4 + cg];
        float4 v1 = xw4[(size_t)s1*4 + cg];
        acc.x = fmaf(v0.x, ds0, acc.x); acc.x = fmaf(v1.x, ds1, acc.x);
        acc.y = fmaf(v0.y, ds0, acc.y); acc.y = fmaf(v1.y, ds1, acc.y);
        acc.z = fmaf(v0.z, ds0, acc.z); acc.z = fmaf(v1.z, ds1, acc.z);
        acc.w = fmaf(v0.w, ds0, acc.w); acc.w = fmaf(v1.w, ds1, acc.w);
    }
    if (j < end){
        int s = g_csr[j];
        float ds = g_dinv[s];
        float4 v = xw4[(size_t)s*4 + cg];
        acc.x = fmaf(v.x, ds, acc.x);
        acc.y = fmaf(v.y, ds, acc.y);
        acc.z = fmaf(v.z, ds, acc.z);
        acc.w = fmaf(v.w, ds, acc.w);
    }
#pragma unroll
    for (int off = 4; off < 32; off <<= 1){
        acc.x += __shfl_xor_sync(0xffffffff, acc.x, off);
        acc.y += __shfl_xor_sync(0xffffffff, acc.y, off);
        acc.z += __shfl_xor_sync(0xffffffff, acc.z, off);
        acc.w += __shfl_xor_sync(0xffffffff, acc.w, off);
    }
    const float* bp = gcnb + cg*4;
    float4 r;
    r.x = lrelu(di*acc.x + bp[0]);
    r.y = lrelu(di*acc.y + bp[1]);
    r.z = lrelu(di*acc.z + bp[2]);
    r.w = lrelu(di*acc.w + bp[3]);

    float hv[16];
    int qb = lane & ~3;
#pragma unroll
    for (int c = 0; c < 4; c++){
        int src = qb + c;
        hv[c*4+0] = __shfl_sync(0xffffffff, r.x, src);
        hv[c*4+1] = __shfl_sync(0xffffffff, r.y, src);
        hv[c*4+2] = __shfl_sync(0xffffffff, r.z, src);
        hv[c*4+3] = __shfl_sync(0xffffffff, r.w, src);
    }
    if (lane < 16){
        float a = 0.f;
#pragma unroll
        for (int i = 0; i < 16; i++) a += hv[i]*Ws[i*16 + lane];
        g_h[(size_t)node*16 + lane] = a * di;
    }
}

// ---------------- gather layer 1 + fused post heads ---------------------------------
__global__ void __launch_bounds__(256)
k_gather2(const float* __restrict__ gcnb,
          const float* __restrict__ po1W, const float* __restrict__ po1b,
          const float* __restrict__ poaW, const float* __restrict__ poab,
          float* __restrict__ out, int out_size){
    int warp = (blockIdx.x*blockDim.x + threadIdx.x) >> 5;
    int lane = threadIdx.x & 31;
    if (warp >= NN) return;
    int node = warp;
    int slot = lane >> 2;
    int cg   = lane & 3;
    int beg = g_rowptr[node], end = g_rowptr[node + 1];
    const float4* xw4 = (const float4*)g_h;

    float4 acc;
    if (slot == 0) acc = xw4[(size_t)node*4 + cg];
    else           acc = make_float4(0.f, 0.f, 0.f, 0.f);

    int j = beg + slot;
    for (; j + 8 < end; j += 16){
        int s0 = g_csr[j];
        int s1 = g_csr[j + 8];
        float4 v0 = xw4[(size_t)s0*4 + cg];
        float4 v1 = xw4[(size_t)s1*4 + cg];
        acc.x += v0.x + v1.x;
        acc.y += v0.y + v1.y;
        acc.z += v0.z + v1.z;
        acc.w += v0.w + v1.w;
    }
    if (j < end){
        int s = g_csr[j];
        float4 v = xw4[(size_t)s*4 + cg];
        acc.x += v.x; acc.y += v.y; acc.z += v.z; acc.w += v.w;
    }
#pragma unroll
    for (int off = 4; off < 32; off <<= 1){
        acc.x += __shfl_xor_sync(0xffffffff, acc.x, off);
        acc.y += __shfl_xor_sync(0xffffffff, acc.y, off);
        acc.z += __shfl_xor_sync(0xffffffff, acc.z, off);
        acc.w += __shfl_xor_sync(0xffffffff, acc.w, off);
    }
    if (lane < 4){
        float di = g_dinv[node];
        const float* bp = gcnb + 16 + cg*4;
        float4 r;
        r.x = lrelu(di*acc.x + bp[0]);
        r.y = lrelu(di*acc.y + bp[1]);
        r.z = lrelu(di*acc.z + bp[2]);
        r.w = lrelu(di*acc.w + bp[3]);
        if (out_size >= 18*NN)
            ((float4*)(out + 2*NN))[(size_t)node*4 + cg] = r;
        int c0 = cg*4;
        float sp = r.x*(po1W[c0+0] + po1W[16+c0+0])
                 + r.y*(po1W[c0+1] + po1W[16+c0+1])
                 + r.z*(po1W[c0+2] + po1W[16+c0+2])
                 + r.w*(po1W[c0+3] + po1W[16+c0+3]);
        float ap = r.x*poaW[c0+0] + r.y*poaW[c0+1]
                 + r.z*poaW[c0+2] + r.w*poaW[c0+3];
        unsigned qm = 0xFu << ((lane >> 2) << 2);
        sp += __shfl_xor_sync(qm, sp, 1); sp += __shfl_xor_sync(qm, sp, 2);
        ap += __shfl_xor_sync(qm, ap, 1); ap += __shfl_xor_sync(qm, ap, 2);
        if (cg == 0){
            out[node] = sp + po1b[0] + po1b[1];
            if (out_size >= 2*NN) out[NN + node] = ap + poab[0];
        }
    }
}

// ---------------- launch --------------------------------------------------------------
extern "C" void kernel_launch(void* const* d_in, const int* in_sizes, int n_in,
                              void* d_out, int out_size){
    const float* x    = (const float*)d_in[0];
    const int*   ei32 = (const int*)d_in[1];
    const float* p1W  = (const float*)d_in[2];
    const float* p1b  = (const float*)d_in[3];
    const float* p2W  = (const float*)d_in[4];
    const float* p2b  = (const float*)d_in[5];
    const float* bih  = (const float*)d_in[6];
    const float* bhh  = (const float*)d_in[7];
    const float* wtW  = (const float*)d_in[8];
    const float* wtb  = (const float*)d_in[9];
    const float* gcnb = (const float*)d_in[10];
    const float* po1W = (const float*)d_in[11];
    const float* po1b = (const float*)d_in[12];
    const float* poaW = (const float*)d_in[13];
    const float* poab = (const float*)d_in[14];
    float* out = (float*)d_out;

    cudaFuncSetAttribute(k_pre, cudaFuncAttributeMaxDynamicSharedMemorySize,
                         PRE_SMEM_BYTES);

    const int NB_N = (NN + 255)/256;
    const int NB_E2 = (NE/2 + 255)/256;
    const int NB_SCAN = (NN + 4095)/4096;   // 25
    const int NB_G = (NN*32 + 255)/256;     // warp per node
    const int NB_I = 2 + (NN + 511)/512;

    cudaStream_t s2 = 0;
    cudaEvent_t  evA = 0, evB = 0;
    bool fork = (cudaStreamCreateWithFlags(&s2, cudaStreamNonBlocking) == cudaSuccess);
    if (fork) fork = (cudaEventCreateWithFlags(&evA, cudaEventDisableTiming) == cudaSuccess);
    if (fork) fork = (cudaEventCreateWithFlags(&evB, cudaEventDisableTiming) == cudaSuccess);

    k_init<<<NB_I, 512>>>(ei32, bih, bhh, wtW, wtb);

    if (fork){
        cudaEventRecord(evA, 0);
        cudaStreamWaitEvent(s2, evA, 0);
        k_edges<<<NB_E2, 256, 0, s2>>>(ei32);
        k_scan1<<<NB_SCAN, 256, 0, s2>>>();
        k_scan3<<<NB_N, 256, 0, s2>>>();
        k_fill <<<NB_E2, 256, 0, s2>>>(ei32);
        cudaEventRecord(evB, s2);
        k_pre  <<<148, 512, PRE_SMEM_BYTES>>>(x, p1W, p1b, p2W, p2b);
        cudaStreamWaitEvent(0, evB, 0);
    } else {
        k_edges<<<NB_E2, 256>>>(ei32);
        k_scan1<<<NB_SCAN, 256>>>();
        k_scan3<<<NB_N, 256>>>();
        k_fill <<<NB_E2, 256>>>(ei32);
        k_pre  <<<148, 512, PRE_SMEM_BYTES>>>(x, p1W, p1b, p2W, p2b);
    }

    k_gather0<<<NB_G, 256>>>(gcnb);
    k_gather2<<<NB_G, 256>>>(gcnb, po1W, po1b, poaW, poab, out, out_size);
}

// round 16
// speedup vs baseline: 1.0785x; 1.0128x over previous
#include <cuda_runtime.h>
#include <cuda_fp16.h>
#include <math.h>

#define NN 100000
#define NE 3200000
#define SLOPE 0.01f

// ---------------- scratch (device globals; no allocation allowed) ----------
__device__ __align__(16) int    g_cnt   [NN];
__device__ __align__(16) int    g_rowptr[NN + 1];
__device__ __align__(16) int    g_next  [NN];
__device__ __align__(16) int    g_bsum  [32];
__device__ __align__(16) int    g_csr   [NE];
__device__ __align__(16) float  g_dinv  [NN];
__device__ __align__(16) __half g_hh    [NN*16];   // xw1 (fp16) after gather0
__device__ __align__(16) __half g_xwh   [NN*16];   // UNSCALED xw0 (fp16) after k_pre
__device__ float g_W[2*256];
__device__ int   g_is64;

__device__ __forceinline__ float lrelu(float v){ return v > 0.f ? v : SLOPE*v; }
__device__ __forceinline__ int   clampi(int v){ return v < 0 ? 0 : (v >= NN ? NN-1 : v); }

// unpack 4 halves (uint2) -> float4
__device__ __forceinline__ float4 h4f(uint2 u){
    __half2 a = *(__half2*)&u.x;
    __half2 b = *(__half2*)&u.y;
    float2 fa = __half22float2(a);
    float2 fb = __half22float2(b);
    return make_float4(fa.x, fa.y, fb.x, fb.y);
}

// packed fp32x2 helpers (Blackwell)
__device__ __forceinline__ unsigned long long pk2(float a, float b){
    unsigned long long r;
    asm("mov.b64 %0, {%1, %2};" : "=l"(r) : "f"(a), "f"(b));
    return r;
}
__device__ __forceinline__ unsigned long long fma2(unsigned long long a,
                                                   unsigned long long b,
                                                   unsigned long long c){
    unsigned long long d;
    asm("fma.rn.f32x2 %0, %1, %2, %3;" : "=l"(d) : "l"(a), "l"(b), "l"(c));
    return d;
}
__device__ __forceinline__ float2 upk2(unsigned long long v){
    float2 r;
    asm("mov.b64 {%0, %1}, %2;" : "=f"(r.x), "=f"(r.y) : "l"(v));
    return r;
}

// ---------------- fused init: block0=dtype detect, block1=hyper, rest=cnt0 ----
__global__ void __launch_bounds__(512)
k_init(const int* __restrict__ ei32,
       const float* __restrict__ bih, const float* __restrict__ bhh,
       const float* __restrict__ wtW, const float* __restrict__ wtb){
    int b = blockIdx.x;
    if (b == 0){
        __shared__ int any;
        if (threadIdx.x == 0) any = 0;
        __syncthreads();
        int v = 0;
#pragma unroll
        for (int q = 0; q < 6; q++){
            int e = threadIdx.x + 512*q;
            v |= ei32[2*e + 1];
        }
        if (v) atomicOr(&any, 1);
        __syncthreads();
        if (threadIdx.x == 0) g_is64 = (any == 0) ? 1 : 0;
    } else if (b == 1){
        int t = threadIdx.x;
        int l = t >> 8, j = t & 255;
        float mem[16];
#pragma unroll
        for (int m = 0; m < 16; m++){
            float r = 1.f/(1.f + expf(-(bih[l*48 + m]      + bhh[l*48 + m])));
            float z = 1.f/(1.f + expf(-(bih[l*48 + 16 + m] + bhh[l*48 + 16 + m])));
            float n = tanhf(bih[l*48 + 32 + m] + r*bhh[l*48 + 32 + m]);
            mem[m] = (1.f - z) * n;
        }
        float acc = wtb[l*256 + j];
#pragma unroll
        for (int m = 0; m < 16; m++) acc += wtW[(l*256 + j)*16 + m] * mem[m];
        g_W[l*256 + j] = acc;
    } else {
        int i = (b - 2)*512 + threadIdx.x;
        if (i < NN) g_cnt[i] = 0;
    }
}

// ---------------- degree count (dst row only); low-reg for co-residency --------
__global__ void __launch_bounds__(256) k_edges(const int* __restrict__ ei32){
    int p = blockIdx.x*blockDim.x + threadIdx.x;
    if (p >= NE/2) return;
    int d0, d1;
    if (g_is64){
        const longlong2* v = (const longlong2*)ei32;
        longlong2 dv = v[(NE >> 1) + p];
        d0 = (int)dv.x; d1 = (int)dv.y;
    } else {
        const int2* v = (const int2*)ei32;
        int2 dv = v[(NE >> 1) + p];
        d0 = dv.x; d1 = dv.y;
    }
    atomicAdd(&g_cnt[clampi(d0)], 1);
    atomicAdd(&g_cnt[clampi(d1)], 1);
}

// ---------------- exclusive scan (+dinv); 256 thr x 16 items, low-reg -----------
__global__ void __launch_bounds__(256) k_scan1(){
    __shared__ int ts[256];
    int b = blockIdx.x, t = threadIdx.x;
    int base = b*4096 + t*16;
    int v[16]; int s = 0;
#pragma unroll
    for (int k = 0; k < 16; k++){
        int idx = base + k;
        v[k] = (idx < NN) ? g_cnt[idx] : 0;
        s += v[k];
        if (idx < NN) g_dinv[idx] = rsqrtf((float)v[k] + 1.0f);
    }
    ts[t] = s; __syncthreads();
#pragma unroll
    for (int off = 1; off < 256; off <<= 1){
        int y = (t >= off) ? ts[t - off] : 0;
        __syncthreads();
        ts[t] += y;
        __syncthreads();
    }
    if (t == 255) g_bsum[b] = ts[255];
    int run = ts[t] - s;
#pragma unroll
    for (int k = 0; k < 16; k++){
        if (base + k < NN) g_rowptr[base + k] = run;
        run += v[k];
    }
}
// scan3 with inline scan2
__global__ void __launch_bounds__(256) k_scan3(){
    __shared__ int bs[32];
    if (threadIdx.x == 0){
        int run = 0;
        for (int j = 0; j < 25; j++){ bs[j] = run; run += g_bsum[j]; }
    }
    __syncthreads();
    int i = blockIdx.x*blockDim.x + threadIdx.x;
    if (i < NN){
        int r = g_rowptr[i] + bs[i >> 12];
        g_rowptr[i] = r;
        g_next[i]   = r;
    }
    if (i == 0) g_rowptr[NN] = NE;
}

// ---------------- CSR fill (2 edges/thread, 16B loads) -----------------------------
__global__ void __launch_bounds__(256) k_fill(const int* __restrict__ ei32){
    int p = blockIdx.x*blockDim.x + threadIdx.x;
    if (p >= NE/2) return;
    int s0, s1, d0, d1;
    if (g_is64){
        const longlong2* v = (const longlong2*)ei32;
        longlong2 sv = v[p];
        longlong2 dv = v[(NE >> 1) + p];
        s0 = (int)sv.x; s1 = (int)sv.y; d0 = (int)dv.x; d1 = (int)dv.y;
    } else {
        const int2* v = (const int2*)ei32;
        int2 sv = v[p];
        int2 dv = v[(NE >> 1) + p];
        s0 = sv.x; s1 = sv.y; d0 = dv.x; d1 = dv.y;
    }
    s0 = clampi(s0); s1 = clampi(s1); d0 = clampi(d0); d1 = clampi(d1);
    int p0 = atomicAdd(&g_next[d0], 1);
    int p1 = atomicAdd(&g_next[d1], 1);
    if (p0 >= 0 && p0 < NE) g_csr[p0] = s0;
    if (p1 >= 0 && p1 < NE) g_csr[p1] = s1;
}

// ---------------- fused preprocess MLP + unscaled xw0 (fp16 out) -------------------
#define P_W1  0         // 32768: blocked w1v[j*256+r] = W1[r][4j..4j+3]
#define P_W2  32768     // 4352 = 256*17 padded transpose
#define P_B2  37120     // 16
#define P_W0  37136     // 256 transposed: W0t[i*16+o] = W0[o][i]
#define P_XG  37392     // 4096: 4 groups x (4 pairs x 128 k x float2)
#define P_H1G 41488     // 8192: 4 groups x (4 pairs x 256 o x float2)
#define P_RG  49680     // 4096: 4 groups x (4 pairs x 8 part x 16 o x float2)
#define PRE_SMEM_FLOATS 53776
#define PRE_SMEM_BYTES  (PRE_SMEM_FLOATS*4)   // 215104

#define GBAR() asm volatile("bar.sync %0, %1;" :: "r"(1 + wg), "r"(128) : "memory")

__global__ void __launch_bounds__(576, 1)
k_pre(const float* __restrict__ x,
      const float* __restrict__ p1W, const float* __restrict__ p1b,
      const float* __restrict__ p2W, const float* __restrict__ p2b){
    extern __shared__ float sm[];
    int t  = threadIdx.x;
    int wg = t >> 7;
    int wt = t & 127;

    {
        float4* w1v = (float4*)(sm + P_W1);
        const float4* p1W4 = (const float4*)p1W;
        for (int i = t; i < 8192; i += 512){
            int j = i >> 8, r = i & 255;
            w1v[i] = p1W4[r*32 + j];
        }
        for (int i = t; i < 4096; i += 512){
            int k = i >> 4, o = i & 15;
            sm[P_W2 + k*17 + o] = p2W[o*256 + k];
        }
        if (t < 16) sm[P_B2 + t] = p2b[t];
        if (t < 256) sm[P_W0 + t] = g_W[(t & 15)*16 + (t >> 4)];
    }

    const int first  = (blockIdx.x*4 + wg)*8;
    const int stride = gridDim.x*32;

    float*  Xg  = sm + P_XG + wg*1024;
    float2* Xw  = (float2*)Xg;
    const ulonglong2* xq = (const ulonglong2*)Xg;
    float2* hbp = (float2*)(sm + P_H1G + wg*2048);
    const unsigned long long* hbu = (const unsigned long long*)(sm + P_H1G + wg*2048);
    unsigned long long* sru = (unsigned long long*)(sm + P_RG + wg*1024);
    const float2* srp = (const float2*)(sm + P_RG + wg*1024);

#pragma unroll
    for (int r = 0; r < 4; r++){
        int e = wt + 128*r, p = e >> 7, k = e & 127;
        Xw[p*128 + k] = make_float2(x[(size_t)(first + 2*p    )*128 + k],
                                    x[(size_t)(first + 2*p + 1)*128 + k]);
    }
    __syncthreads();

    float b0 = p1b[wt], b1 = p1b[128 + wt];

    for (int base = first; base < NN; base += stride){
        int nbase = base + stride;
        bool hasnext = (nbase < NN);

        float2 nx0, nx1, nx2, nx3;
        if (hasnext){
            nx0 = make_float2(x[(size_t)(nbase    )*128 + wt], x[(size_t)(nbase + 1)*128 + wt]);
            nx1 = make_float2(x[(size_t)(nbase + 2)*128 + wt], x[(size_t)(nbase + 3)*128 + wt]);
            nx2 = make_float2(x[(size_t)(nbase + 4)*128 + wt], x[(size_t)(nbase + 5)*128 + wt]);
            nx3 = make_float2(x[(size_t)(nbase + 6)*128 + wt], x[(size_t)(nbase + 7)*128 + wt]);
        }

        unsigned long long a00, a01, a02, a03, a10, a11, a12, a13;
        a00 = a01 = a02 = a03 = pk2(b0, b0);
        a10 = a11 = a12 = a13 = pk2(b1, b1);
        const float4* wv = (const float4*)(sm + P_W1);
#pragma unroll 2
        for (int j = 0; j < 32; j++){
            float4 wA = wv[j*256 + wt];
            float4 wB = wv[j*256 + 128 + wt];
            ulonglong2 x0a = xq[0*64 + 2*j], x0b = xq[0*64 + 2*j + 1];
            ulonglong2 x1a = xq[1*64 + 2*j], x1b = xq[1*64 + 2*j + 1];
            ulonglong2 x2a = xq[2*64 + 2*j], x2b = xq[2*64 + 2*j + 1];
            ulonglong2 x3a = xq[3*64 + 2*j], x3b = xq[3*64 + 2*j + 1];
            unsigned long long wA0 = pk2(wA.x, wA.x), wA1 = pk2(wA.y, wA.y);
            unsigned long long wA2 = pk2(wA.z, wA.z), wA3 = pk2(wA.w, wA.w);
            a00 = fma2(wA0, x0a.x, a00); a00 = fma2(wA1, x0a.y, a00);
            a00 = fma2(wA2, x0b.x, a00); a00 = fma2(wA3, x0b.y, a00);
            a01 = fma2(wA0, x1a.x, a01); a01 = fma2(wA1, x1a.y, a01);
            a01 = fma2(wA2, x1b.x, a01); a01 = fma2(wA3, x1b.y, a01);
            a02 = fma2(wA0, x2a.x, a02); a02 = fma2(wA1, x2a.y, a02);
            a02 = fma2(wA2, x2b.x, a02); a02 = fma2(wA3, x2b.y, a02);
            a03 = fma2(wA0, x3a.x, a03); a03 = fma2(wA1, x3a.y, a03);
            a03 = fma2(wA2, x3b.x, a03); a03 = fma2(wA3, x3b.y, a03);
            unsigned long long wB0 = pk2(wB.x, wB.x), wB1 = pk2(wB.y, wB.y);
            unsigned long long wB2 = pk2(wB.z, wB.z), wB3 = pk2(wB.w, wB.w);
            a10 = fma2(wB0, x0a.x, a10); a10 = fma2(wB1, x0a.y, a10);
            a10 = fma2(wB2, x0b.x, a10); a10 = fma2(wB3, x0b.y, a10);
            a11 = fma2(wB0, x1a.x, a11); a11 = fma2(wB1, x1a.y, a11);
            a11 = fma2(wB2, x1b.x, a11); a11 = fma2(wB3, x1b.y, a11);
            a12 = fma2(wB0, x2a.x, a12); a12 = fma2(wB1, x2a.y, a12);
            a12 = fma2(wB2, x2b.x, a12); a12 = fma2(wB3, x2b.y, a12);
            a13 = fma2(wB0, x3a.x, a13); a13 = fma2(wB1, x3a.y, a13);
            a13 = fma2(wB2, x3b.x, a13); a13 = fma2(wB3, x3b.y, a13);
        }
        {
            float2 y;
            y = upk2(a00); hbp[0*256 + wt]       = make_float2(lrelu(y.x), lrelu(y.y));
            y = upk2(a01); hbp[1*256 + wt]       = make_float2(lrelu(y.x), lrelu(y.y));
            y = upk2(a02); hbp[2*256 + wt]       = make_float2(lrelu(y.x), lrelu(y.y));
            y = upk2(a03); hbp[3*256 + wt]       = make_float2(lrelu(y.x), lrelu(y.y));
            y = upk2(a10); hbp[0*256 + 128 + wt] = make_float2(lrelu(y.x), lrelu(y.y));
            y = upk2(a11); hbp[1*256 + 128 + wt] = make_float2(lrelu(y.x), lrelu(y.y));
            y = upk2(a12); hbp[2*256 + 128 + wt] = make_float2(lrelu(y.x), lrelu(y.y));
            y = upk2(a13); hbp[3*256 + 128 + wt] = make_float2(lrelu(y.x), lrelu(y.y));
        }
        GBAR();   // h1 visible; X consumed

        if (hasnext){
            Xw[0*128 + wt] = nx0;
            Xw[1*128 + wt] = nx1;
            Xw[2*128 + wt] = nx2;
            Xw[3*128 + wt] = nx3;
        }
        {
            int o = wt & 15, part = wt >> 4;
            unsigned long long c0 = 0ULL, c1 = 0ULL, c2 = 0ULL, c3 = 0ULL;
#pragma unroll
            for (int kk = 0; kk < 32; kk++){
                int k = part*32 + kk;
                float w2s = sm[P_W2 + k*17 + o];
                unsigned long long w2 = pk2(w2s, w2s);
                c0 = fma2(w2, hbu[0*256 + k], c0);
                c1 = fma2(w2, hbu[1*256 + k], c1);
                c2 = fma2(w2, hbu[2*256 + k], c2);
                c3 = fma2(w2, hbu[3*256 + k], c3);
            }
            sru[0*128 + part*16 + o] = c0;
            sru[1*128 + part*16 + o] = c1;
            sru[2*128 + part*16 + o] = c2;
            sru[3*128 + part*16 + o] = c3;
        }
        GBAR();   // partials visible; X stable for next iter

        // merged epilogue: final h + unscaled xw0 (fp16) via warp shuffles
        if (wt < 64){
            int p = wt >> 4, o = wt & 15;
            float sx = 0.f, sy = 0.f;
#pragma unroll
            for (int q = 0; q < 8; q++){
                float2 v = srp[p*128 + q*16 + o];
                sx += v.x; sy += v.y;
            }
            float bb2 = sm[P_B2 + o];
            sx += bb2; sy += bb2;
            sx = fmaxf(sx, SLOPE*sx);
            sy = fmaxf(sy, SLOPE*sy);
            float ax = 0.f, ay = 0.f;
            int sb = (p & 1) << 4;
#pragma unroll
            for (int i = 0; i < 16; i++){
                float hx = __shfl_sync(0xffffffffu, sx, sb + i);
                float hy = __shfl_sync(0xffffffffu, sy, sb + i);
                float w = sm[P_W0 + i*16 + o];
                ax = fmaf(hx, w, ax);
                ay = fmaf(hy, w, ay);
            }
            int n0 = base + 2*p;
            g_xwh[(size_t)n0*16 + o]       = __float2half(ax);
            g_xwh[(size_t)(n0 + 1)*16 + o] = __float2half(ay);
        }
        // no barrier: sru rewritten only after next iter's GBAR(1).
    }
}

// ---------------- gather layer 0 (dinv per edge) + fused xw1 (fp16 out) -------------
__global__ void __launch_bounds__(256)
k_gather0(const float* __restrict__ gcnb){
    __shared__ float Ws[256];   // W1 (gcn layer1) transposed
    Ws[threadIdx.x] = g_W[256 + (threadIdx.x & 15)*16 + (threadIdx.x >> 4)];
    __syncthreads();

    int warp = (blockIdx.x*blockDim.x + threadIdx.x) >> 5;
    int lane = threadIdx.x & 31;
    if (warp >= NN) return;
    int node = warp;
    int slot = lane >> 2;
    int cg   = lane & 3;
    int beg = g_rowptr[node], end = g_rowptr[node + 1];
    const uint2* xwh = (const uint2*)g_xwh;   // 4 halves per element
    float di = g_dinv[node];

    float4 acc;
    if (slot == 0){
        float4 v = h4f(xwh[(size_t)node*4 + cg]);
        acc = make_float4(v.x*di, v.y*di, v.z*di, v.w*di);
    } else {
        acc = make_float4(0.f, 0.f, 0.f, 0.f);
    }

    int j = beg + slot;
    for (; j + 8 < end; j += 16){
        int s0 = g_csr[j];
        int s1 = g_csr[j + 8];
        float ds0 = g_dinv[s0];
        float ds1 = g_dinv[s1];
        float4 v0 = h4f(xwh[(size_t)s0*4 + cg]);
        float4 v1 = h4f(xwh[(size_t)s1*4 + cg]);
        acc.x = fmaf(v0.x, ds0, acc.x); acc.x = fmaf(v1.x, ds1, acc.x);
        acc.y = fmaf(v0.y, ds0, acc.y); acc.y = fmaf(v1.y, ds1, acc.y);
        acc.z = fmaf(v0.z, ds0, acc.z); acc.z = fmaf(v1.z, ds1, acc.z);
        acc.w = fmaf(v0.w, ds0, acc.w); acc.w = fmaf(v1.w, ds1, acc.w);
    }
    if (j < end){
        int s = g_csr[j];
        float ds = g_dinv[s];
        float4 v = h4f(xwh[(size_t)s*4 + cg]);
        acc.x = fmaf(v.x, ds, acc.x);
        acc.y = fmaf(v.y, ds, acc.y);
        acc.z = fmaf(v.z, ds, acc.z);
        acc.w = fmaf(v.w, ds, acc.w);
    }
#pragma unroll
    for (int off = 4; off < 32; off <<= 1){
        acc.x += __shfl_xor_sync(0xffffffff, acc.x, off);
        acc.y += __shfl_xor_sync(0xffffffff, acc.y, off);
        acc.z += __shfl_xor_sync(0xffffffff, acc.z, off);
        acc.w += __shfl_xor_sync(0xffffffff, acc.w, off);
    }
    const float* bp = gcnb + cg*4;
    float4 r;
    r.x = lrelu(di*acc.x + bp[0]);
    r.y = lrelu(di*acc.y + bp[1]);
    r.z = lrelu(di*acc.z + bp[2]);
    r.w = lrelu(di*acc.w + bp[3]);

    float hv[16];
    int qb = lane & ~3;
#pragma unroll
    for (int c = 0; c < 4; c++){
        int src = qb + c;
        hv[c*4+0] = __shfl_sync(0xffffffff, r.x, src);
        hv[c*4+1] = __shfl_sync(0xffffffff, r.y, src);
        hv[c*4+2] = __shfl_sync(0xffffffff, r.z, src);
        hv[c*4+3] = __shfl_sync(0xffffffff, r.w, src);
    }
    if (lane < 16){
        float a = 0.f;
#pragma unroll
        for (int i = 0; i < 16; i++) a += hv[i]*Ws[i*16 + lane];
        g_hh[(size_t)node*16 + lane] = __float2half(a * di);
    }
}

// ---------------- gather layer 1 + fused post heads ---------------------------------
__global__ void __launch_bounds__(256)
k_gather2(const float* __restrict__ gcnb,
          const float* __restrict__ po1W, const float* __restrict__ po1b,
          const float* __restrict__ poaW, const float* __restrict__ poab,
          float* __restrict__ out, int out_size){
    int warp = (blockIdx.x*blockDim.x + threadIdx.x) >> 5;
    int lane = threadIdx.x & 31;
    if (warp >= NN) return;
    int node = warp;
    int slot = lane >> 2;
    int cg   = lane & 3;
    int beg = g_rowptr[node], end = g_rowptr[node + 1];
    const uint2* xwh = (const uint2*)g_hh;

    float4 acc;
    if (slot == 0) acc = h4f(xwh[(size_t)node*4 + cg]);
    else           acc = make_float4(0.f, 0.f, 0.f, 0.f);

    int j = beg + slot;
    for (; j + 8 < end; j += 16){
        int s0 = g_csr[j];
        int s1 = g_csr[j + 8];
        float4 v0 = h4f(xwh[(size_t)s0*4 + cg]);
        float4 v1 = h4f(xwh[(size_t)s1*4 + cg]);
        acc.x += v0.x + v1.x;
        acc.y += v0.y + v1.y;
        acc.z += v0.z + v1.z;
        acc.w += v0.w + v1.w;
    }
    if (j < end){
        int s = g_csr[j];
        float4 v = h4f(xwh[(size_t)s*4 + cg]);
        acc.x += v.x; acc.y += v.y; acc.z += v.z; acc.w += v.w;
    }
#pragma unroll
    for (int off = 4; off < 32; off <<= 1){
        acc.x += __shfl_xor_sync(0xffffffff, acc.x, off);
        acc.y += __shfl_xor_sync(0xffffffff, acc.y, off);
        acc.z += __shfl_xor_sync(0xffffffff, acc.z, off);
        acc.w += __shfl_xor_sync(0xffffffff, acc.w, off);
    }
    if (lane < 4){
        float di = g_dinv[node];
        const float* bp = gcnb + 16 + cg*4;
        float4 r;
        r.x = lrelu(di*acc.x + bp[0]);
        r.y = lrelu(di*acc.y + bp[1]);
        r.z = lrelu(di*acc.z + bp[2]);
        r.w = lrelu(di*acc.w + bp[3]);
        if (out_size >= 18*NN)
            ((float4*)(out + 2*NN))[(size_t)node*4 + cg] = r;
        int c0 = cg*4;
        float sp = r.x*(po1W[c0+0] + po1W[16+c0+0])
                 + r.y*(po1W[c0+1] + po1W[16+c0+1])
                 + r.z*(po1W[c0+2] + po1W[16+c0+2])
                 + r.w*(po1W[c0+3] + po1W[16+c0+3]);
        float ap = r.x*poaW[c0+0] + r.y*poaW[c0+1]
                 + r.z*poaW[c0+2] + r.w*poaW[c0+3];
        unsigned qm = 0xFu << ((lane >> 2) << 2);
        sp += __shfl_xor_sync(qm, sp, 1); sp += __shfl_xor_sync(qm, sp, 2);
        ap += __shfl_xor_sync(qm, ap, 1); ap += __shfl_xor_sync(qm, ap, 2);
        if (cg == 0){
            out[node] = sp + po1b[0] + po1b[1];
            if (out_size >= 2*NN) out[NN + node] = ap + poab[0];
        }
    }
}

// ---------------- launch --------------------------------------------------------------
extern "C" void kernel_launch(void* const* d_in, const int* in_sizes, int n_in,
                              void* d_out, int out_size){
    const float* x    = (const float*)d_in[0];
    const int*   ei32 = (const int*)d_in[1];
    const float* p1W  = (const float*)d_in[2];
    const float* p1b  = (const float*)d_in[3];
    const float* p2W  = (const float*)d_in[4];
    const float* p2b  = (const float*)d_in[5];
    const float* bih  = (const float*)d_in[6];
    const float* bhh  = (const float*)d_in[7];
    const float* wtW  = (const float*)d_in[8];
    const float* wtb  = (const float*)d_in[9];
    const float* gcnb = (const float*)d_in[10];
    const float* po1W = (const float*)d_in[11];
    const float* po1b = (const float*)d_in[12];
    const float* poaW = (const float*)d_in[13];
    const float* poab = (const float*)d_in[14];
    float* out = (float*)d_out;

    cudaFuncSetAttribute(k_pre, cudaFuncAttributeMaxDynamicSharedMemorySize,
                         PRE_SMEM_BYTES);

    const int NB_N = (NN + 255)/256;
    const int NB_E2 = (NE/2 + 255)/256;
    const int NB_SCAN = (NN + 4095)/4096;   // 25
    const int NB_G = (NN*32 + 255)/256;     // warp per node
    const int NB_I = 2 + (NN + 511)/512;

    cudaStream_t s2 = 0;
    cudaEvent_t  evA = 0, evB = 0;
    bool fork = (cudaStreamCreateWithFlags(&s2, cudaStreamNonBlocking) == cudaSuccess);
    if (fork) fork = (cudaEventCreateWithFlags(&evA, cudaEventDisableTiming) == cudaSuccess);
    if (fork) fork = (cudaEventCreateWithFlags(&evB, cudaEventDisableTiming) == cudaSuccess);

    k_init<<<NB_I, 512>>>(ei32, bih, bhh, wtW, wtb);

    if (fork){
        cudaEventRecord(evA, 0);
        cudaStreamWaitEvent(s2, evA, 0);
        k_edges<<<NB_E2, 256, 0, s2>>>(ei32);
        k_scan1<<<NB_SCAN, 256, 0, s2>>>();
        k_scan3<<<NB_N, 256, 0, s2>>>();
        k_fill <<<NB_E2, 256, 0, s2>>>(ei32);
        cudaEventRecord(evB, s2);
        k_pre  <<<148, 512, PRE_SMEM_BYTES>>>(x, p1W, p1b, p2W, p2b);
        cudaStreamWaitEvent(0, evB, 0);
    } else {
        k_edges<<<NB_E2, 256>>>(ei32);
        k_scan1<<<NB_SCAN, 256>>>();
        k_scan3<<<NB_N, 256>>>();
        k_fill <<<NB_E2, 256>>>(ei32);
        k_pre  <<<148, 512, PRE_SMEM_BYTES>>>(x, p1W, p1b, p2W, p2b);
    }

    k_gather0<<<NB_G, 256>>>(gcnb);
    k_gather2<<<NB_G, 256>>>(gcnb, po1W, po1b, poaW, poab, out, out_size);
}

// round 17
// speedup vs baseline: 1.0944x; 1.0147x over previous
#include <cuda_runtime.h>
#include <cuda_fp16.h>
#include <math.h>

#define NN 100000
#define NE 3200000
#define SLOPE 0.01f

// ---------------- scratch (device globals; no allocation allowed) ----------
__device__ __align__(16) int    g_cnt   [NN];
__device__ __align__(16) int    g_rowptr[NN + 1];
__device__ __align__(16) int    g_next  [NN];
__device__ __align__(16) int    g_bsum  [32];
__device__ __align__(16) int    g_csr   [NE];
__device__ __align__(16) float  g_dinv  [NN];
__device__ __align__(16) __half g_hh    [NN*16];   // xw1 (fp16) after gather0
__device__ __align__(16) __half g_xwh   [NN*16];   // UNSCALED xw0 (fp16) after k_pre
__device__ float g_W[2*256];
__device__ int   g_is64;

__device__ __forceinline__ float lrelu(float v){ return v > 0.f ? v : SLOPE*v; }
__device__ __forceinline__ int   clampi(int v){ return v < 0 ? 0 : (v >= NN ? NN-1 : v); }

// unpack 4 halves (uint2) -> float4
__device__ __forceinline__ float4 h4f(uint2 u){
    __half2 a = *(__half2*)&u.x;
    __half2 b = *(__half2*)&u.y;
    float2 fa = __half22float2(a);
    float2 fb = __half22float2(b);
    return make_float4(fa.x, fa.y, fb.x, fb.y);
}

// packed fp32x2 helpers (Blackwell)
__device__ __forceinline__ unsigned long long pk2(float a, float b){
    unsigned long long r;
    asm("mov.b64 %0, {%1, %2};" : "=l"(r) : "f"(a), "f"(b));
    return r;
}
__device__ __forceinline__ unsigned long long fma2(unsigned long long a,
                                                   unsigned long long b,
                                                   unsigned long long c){
    unsigned long long d;
    asm("fma.rn.f32x2 %0, %1, %2, %3;" : "=l"(d) : "l"(a), "l"(b), "l"(c));
    return d;
}
__device__ __forceinline__ float2 upk2(unsigned long long v){
    float2 r;
    asm("mov.b64 {%0, %1}, %2;" : "=f"(r.x), "=f"(r.y) : "l"(v));
    return r;
}

// ---------------- fused init: block0=dtype detect, block1=hyper, rest=cnt0 ----
__global__ void __launch_bounds__(512)
k_init(const int* __restrict__ ei32,
       const float* __restrict__ bih, const float* __restrict__ bhh,
       const float* __restrict__ wtW, const float* __restrict__ wtb){
    int b = blockIdx.x;
    if (b == 0){
        __shared__ int any;
        if (threadIdx.x == 0) any = 0;
        __syncthreads();
        int v = 0;
#pragma unroll
        for (int q = 0; q < 6; q++){
            int e = threadIdx.x + 512*q;
            v |= ei32[2*e + 1];
        }
        if (v) atomicOr(&any, 1);
        __syncthreads();
        if (threadIdx.x == 0) g_is64 = (any == 0) ? 1 : 0;
    } else if (b == 1){
        int t = threadIdx.x;
        int l = t >> 8, j = t & 255;
        float mem[16];
#pragma unroll
        for (int m = 0; m < 16; m++){
            float r = 1.f/(1.f + expf(-(bih[l*48 + m]      + bhh[l*48 + m])));
            float z = 1.f/(1.f + expf(-(bih[l*48 + 16 + m] + bhh[l*48 + 16 + m])));
            float n = tanhf(bih[l*48 + 32 + m] + r*bhh[l*48 + 32 + m]);
            mem[m] = (1.f - z) * n;
        }
        float acc = wtb[l*256 + j];
#pragma unroll
        for (int m = 0; m < 16; m++) acc += wtW[(l*256 + j)*16 + m] * mem[m];
        g_W[l*256 + j] = acc;
    } else {
        int i = (b - 2)*512 + threadIdx.x;
        if (i < NN) g_cnt[i] = 0;
    }
}

// ---------------- degree count (dst row only); low-reg for co-residency --------
__global__ void __launch_bounds__(256) k_edges(const int* __restrict__ ei32){
    int p = blockIdx.x*blockDim.x + threadIdx.x;
    if (p >= NE/2) return;
    int d0, d1;
    if (g_is64){
        const longlong2* v = (const longlong2*)ei32;
        longlong2 dv = v[(NE >> 1) + p];
        d0 = (int)dv.x; d1 = (int)dv.y;
    } else {
        const int2* v = (const int2*)ei32;
        int2 dv = v[(NE >> 1) + p];
        d0 = dv.x; d1 = dv.y;
    }
    atomicAdd(&g_cnt[clampi(d0)], 1);
    atomicAdd(&g_cnt[clampi(d1)], 1);
}

// ---------------- exclusive scan (+dinv); 256 thr x 16 items, low-reg -----------
__global__ void __launch_bounds__(256) k_scan1(){
    __shared__ int ts[256];
    int b = blockIdx.x, t = threadIdx.x;
    int base = b*4096 + t*16;
    int v[16]; int s = 0;
#pragma unroll
    for (int k = 0; k < 16; k++){
        int idx = base + k;
        v[k] = (idx < NN) ? g_cnt[idx] : 0;
        s += v[k];
        if (idx < NN) g_dinv[idx] = rsqrtf((float)v[k] + 1.0f);
    }
    ts[t] = s; __syncthreads();
#pragma unroll
    for (int off = 1; off < 256; off <<= 1){
        int y = (t >= off) ? ts[t - off] : 0;
        __syncthreads();
        ts[t] += y;
        __syncthreads();
    }
    if (t == 255) g_bsum[b] = ts[255];
    int run = ts[t] - s;
#pragma unroll
    for (int k = 0; k < 16; k++){
        if (base + k < NN) g_rowptr[base + k] = run;
        run += v[k];
    }
}
// scan3 with inline scan2
__global__ void __launch_bounds__(256) k_scan3(){
    __shared__ int bs[32];
    if (threadIdx.x == 0){
        int run = 0;
        for (int j = 0; j < 25; j++){ bs[j] = run; run += g_bsum[j]; }
    }
    __syncthreads();
    int i = blockIdx.x*blockDim.x + threadIdx.x;
    if (i < NN){
        int r = g_rowptr[i] + bs[i >> 12];
        g_rowptr[i] = r;
        g_next[i]   = r;
    }
    if (i == 0) g_rowptr[NN] = NE;
}

// ---------------- CSR fill (2 edges/thread, 16B loads) -----------------------------
__global__ void __launch_bounds__(256) k_fill(const int* __restrict__ ei32){
    int p = blockIdx.x*blockDim.x + threadIdx.x;
    if (p >= NE/2) return;
    int s0, s1, d0, d1;
    if (g_is64){
        const longlong2* v = (const longlong2*)ei32;
        longlong2 sv = v[p];
        longlong2 dv = v[(NE >> 1) + p];
        s0 = (int)sv.x; s1 = (int)sv.y; d0 = (int)dv.x; d1 = (int)dv.y;
    } else {
        const int2* v = (const int2*)ei32;
        int2 sv = v[p];
        int2 dv = v[(NE >> 1) + p];
        s0 = sv.x; s1 = sv.y; d0 = dv.x; d1 = dv.y;
    }
    s0 = clampi(s0); s1 = clampi(s1); d0 = clampi(d0); d1 = clampi(d1);
    int p0 = atomicAdd(&g_next[d0], 1);
    int p1 = atomicAdd(&g_next[d1], 1);
    if (p0 >= 0 && p0 < NE) g_csr[p0] = s0;
    if (p1 >= 0 && p1 < NE) g_csr[p1] = s1;
}

// ---------------- fused preprocess MLP + unscaled xw0 (fp16 out) -------------------
// 4 groups x 128 thr; layer-2 uses k-paired float2 W2 + 16B h loads (3 wf/kk).
#define P_W1  0         // 32768: blocked w1v[j*256+r] = W1[r][4j..4j+3]
#define P_W2  32768     // 4352 floats = float2 W2P[128][17]: W2P[kp*17+o]={W2[o][2kp],W2[o][2kp+1]}
#define P_B2  37120     // 16
#define P_W0  37136     // 256 transposed: W0t[i*16+o] = W0[o][i]
#define P_XG  37392     // 4096: 4 groups x (4 pairs x 128 k x float2)
#define P_H1G 41488     // 8192: 4 groups x (4 pairs x 256 o x float2)
#define P_RG  49680     // 4096: 4 groups x (4 pairs x 8 part x 16 o x float2)
#define PRE_SMEM_FLOATS 53776
#define PRE_SMEM_BYTES  (PRE_SMEM_FLOATS*4)   // 215104

#define GBAR() asm volatile("bar.sync %0, %1;" :: "r"(1 + wg), "r"(128) : "memory")

__global__ void __launch_bounds__(576, 1)
k_pre(const float* __restrict__ x,
      const float* __restrict__ p1W, const float* __restrict__ p1b,
      const float* __restrict__ p2W, const float* __restrict__ p2b){
    extern __shared__ float sm[];
    int t  = threadIdx.x;
    int wg = t >> 7;
    int wt = t & 127;

    {
        float4* w1v = (float4*)(sm + P_W1);
        const float4* p1W4 = (const float4*)p1W;
        for (int i = t; i < 8192; i += 512){
            int j = i >> 8, r = i & 255;
            w1v[i] = p1W4[r*32 + j];
        }
        float2* w2p = (float2*)(sm + P_W2);
        for (int i = t; i < 2048; i += 512){
            int kp = i >> 4, o = i & 15;
            w2p[kp*17 + o] = make_float2(p2W[o*256 + 2*kp], p2W[o*256 + 2*kp + 1]);
        }
        if (t < 16) sm[P_B2 + t] = p2b[t];
        if (t < 256) sm[P_W0 + t] = g_W[(t & 15)*16 + (t >> 4)];
    }

    const int first  = (blockIdx.x*4 + wg)*8;
    const int stride = gridDim.x*32;

    float*  Xg  = sm + P_XG + wg*1024;
    float4* Xw4 = (float4*)Xg;
    const ulonglong2* xq = (const ulonglong2*)Xg;
    float2* hbp = (float2*)(sm + P_H1G + wg*2048);
    const ulonglong2* hbu2 = (const ulonglong2*)(sm + P_H1G + wg*2048);
    unsigned long long* sru = (unsigned long long*)(sm + P_RG + wg*1024);
    const float2* srp = (const float2*)(sm + P_RG + wg*1024);
    const float2* w2p = (const float2*)(sm + P_W2);

    int pr = wt >> 5;     // pair 0..3 (for x staging)
    int cc = wt & 31;     // float4 column 0..31

    // initial X fill for first batch (vectorized, interleave pairs)
    {
        const float4* x4 = (const float4*)x;
        float4 xa = x4[(size_t)(first + 2*pr)*32 + cc];
        float4 xb = x4[(size_t)(first + 2*pr + 1)*32 + cc];
        Xw4[pr*64 + 2*cc]     = make_float4(xa.x, xb.x, xa.y, xb.y);
        Xw4[pr*64 + 2*cc + 1] = make_float4(xa.z, xb.z, xa.w, xb.w);
    }
    __syncthreads();

    float b0 = p1b[wt], b1 = p1b[128 + wt];

    for (int base = first; base < NN; base += stride){
        int nbase = base + stride;
        bool hasnext = (nbase < NN);

        float4 xa, xb;
        if (hasnext){
            const float4* x4 = (const float4*)x;
            xa = x4[(size_t)(nbase + 2*pr)*32 + cc];
            xb = x4[(size_t)(nbase + 2*pr + 1)*32 + cc];
        }

        unsigned long long a00, a01, a02, a03, a10, a11, a12, a13;
        a00 = a01 = a02 = a03 = pk2(b0, b0);
        a10 = a11 = a12 = a13 = pk2(b1, b1);
        const float4* wv = (const float4*)(sm + P_W1);
#pragma unroll 2
        for (int j = 0; j < 32; j++){
            float4 wA = wv[j*256 + wt];
            float4 wB = wv[j*256 + 128 + wt];
            ulonglong2 x0a = xq[0*64 + 2*j], x0b = xq[0*64 + 2*j + 1];
            ulonglong2 x1a = xq[1*64 + 2*j], x1b = xq[1*64 + 2*j + 1];
            ulonglong2 x2a = xq[2*64 + 2*j], x2b = xq[2*64 + 2*j + 1];
            ulonglong2 x3a = xq[3*64 + 2*j], x3b = xq[3*64 + 2*j + 1];
            unsigned long long wA0 = pk2(wA.x, wA.x), wA1 = pk2(wA.y, wA.y);
            unsigned long long wA2 = pk2(wA.z, wA.z), wA3 = pk2(wA.w, wA.w);
            a00 = fma2(wA0, x0a.x, a00); a00 = fma2(wA1, x0a.y, a00);
            a00 = fma2(wA2, x0b.x, a00); a00 = fma2(wA3, x0b.y, a00);
            a01 = fma2(wA0, x1a.x, a01); a01 = fma2(wA1, x1a.y, a01);
            a01 = fma2(wA2, x1b.x, a01); a01 = fma2(wA3, x1b.y, a01);
            a02 = fma2(wA0, x2a.x, a02); a02 = fma2(wA1, x2a.y, a02);
            a02 = fma2(wA2, x2b.x, a02); a02 = fma2(wA3, x2b.y, a02);
            a03 = fma2(wA0, x3a.x, a03); a03 = fma2(wA1, x3a.y, a03);
            a03 = fma2(wA2, x3b.x, a03); a03 = fma2(wA3, x3b.y, a03);
            unsigned long long wB0 = pk2(wB.x, wB.x), wB1 = pk2(wB.y, wB.y);
            unsigned long long wB2 = pk2(wB.z, wB.z), wB3 = pk2(wB.w, wB.w);
            a10 = fma2(wB0, x0a.x, a10); a10 = fma2(wB1, x0a.y, a10);
            a10 = fma2(wB2, x0b.x, a10); a10 = fma2(wB3, x0b.y, a10);
            a11 = fma2(wB0, x1a.x, a11); a11 = fma2(wB1, x1a.y, a11);
            a11 = fma2(wB2, x1b.x, a11); a11 = fma2(wB3, x1b.y, a11);
            a12 = fma2(wB0, x2a.x, a12); a12 = fma2(wB1, x2a.y, a12);
            a12 = fma2(wB2, x2b.x, a12); a12 = fma2(wB3, x2b.y, a12);
            a13 = fma2(wB0, x3a.x, a13); a13 = fma2(wB1, x3a.y, a13);
            a13 = fma2(wB2, x3b.x, a13); a13 = fma2(wB3, x3b.y, a13);
        }
        {
            float2 y;
            y = upk2(a00); hbp[0*256 + wt]       = make_float2(lrelu(y.x), lrelu(y.y));
            y = upk2(a01); hbp[1*256 + wt]       = make_float2(lrelu(y.x), lrelu(y.y));
            y = upk2(a02); hbp[2*256 + wt]       = make_float2(lrelu(y.x), lrelu(y.y));
            y = upk2(a03); hbp[3*256 + wt]       = make_float2(lrelu(y.x), lrelu(y.y));
            y = upk2(a10); hbp[0*256 + 128 + wt] = make_float2(lrelu(y.x), lrelu(y.y));
            y = upk2(a11); hbp[1*256 + 128 + wt] = make_float2(lrelu(y.x), lrelu(y.y));
            y = upk2(a12); hbp[2*256 + 128 + wt] = make_float2(lrelu(y.x), lrelu(y.y));
            y = upk2(a13); hbp[3*256 + 128 + wt] = make_float2(lrelu(y.x), lrelu(y.y));
        }
        GBAR();   // h1 visible; X consumed

        if (hasnext){
            Xw4[pr*64 + 2*cc]     = make_float4(xa.x, xb.x, xa.y, xb.y);
            Xw4[pr*64 + 2*cc + 1] = make_float4(xa.z, xb.z, xa.w, xb.w);
        }
        {
            // layer 2: k-paired loads. thread (o, part); kp = part*16 + s
            int o = wt & 15, part = wt >> 4;
            unsigned long long c0 = 0ULL, c1 = 0ULL, c2 = 0ULL, c3 = 0ULL;
#pragma unroll
            for (int s = 0; s < 16; s++){
                int kp = part*16 + s;
                float2 w2 = w2p[kp*17 + o];
                unsigned long long w2a = pk2(w2.x, w2.x);
                unsigned long long w2b = pk2(w2.y, w2.y);
                ulonglong2 h0 = hbu2[0*128 + kp];
                ulonglong2 h1 = hbu2[1*128 + kp];
                ulonglong2 h2 = hbu2[2*128 + kp];
                ulonglong2 h3 = hbu2[3*128 + kp];
                c0 = fma2(w2a, h0.x, c0); c0 = fma2(w2b, h0.y, c0);
                c1 = fma2(w2a, h1.x, c1); c1 = fma2(w2b, h1.y, c1);
                c2 = fma2(w2a, h2.x, c2); c2 = fma2(w2b, h2.y, c2);
                c3 = fma2(w2a, h3.x, c3); c3 = fma2(w2b, h3.y, c3);
            }
            sru[0*128 + part*16 + o] = c0;
            sru[1*128 + part*16 + o] = c1;
            sru[2*128 + part*16 + o] = c2;
            sru[3*128 + part*16 + o] = c3;
        }
        GBAR();   // partials visible; X stable for next iter

        // merged epilogue: final h + unscaled xw0 (fp16) via warp shuffles
        if (wt < 64){
            int p = wt >> 4, o = wt & 15;
            float sx = 0.f, sy = 0.f;
#pragma unroll
            for (int q = 0; q < 8; q++){
                float2 v = srp[p*128 + q*16 + o];
                sx += v.x; sy += v.y;
            }
            float bb2 = sm[P_B2 + o];
            sx += bb2; sy += bb2;
            sx = fmaxf(sx, SLOPE*sx);
            sy = fmaxf(sy, SLOPE*sy);
            float ax = 0.f, ay = 0.f;
            int sb = (p & 1) << 4;
#pragma unroll
            for (int i = 0; i < 16; i++){
                float hx = __shfl_sync(0xffffffffu, sx, sb + i);
                float hy = __shfl_sync(0xffffffffu, sy, sb + i);
                float w = sm[P_W0 + i*16 + o];
                ax = fmaf(hx, w, ax);
                ay = fmaf(hy, w, ay);
            }
            int n0 = base + 2*p;
            g_xwh[(size_t)n0*16 + o]       = __float2half(ax);
            g_xwh[(size_t)(n0 + 1)*16 + o] = __float2half(ay);
        }
        // no barrier: sru rewritten only after next iter's GBAR(1).
    }
}

// ---------------- gather layer 0 (dinv per edge) + fused xw1 (fp16 out) -------------
__global__ void __launch_bounds__(256)
k_gather0(const float* __restrict__ gcnb){
    __shared__ float Ws[256];   // W1 (gcn layer1) transposed
    Ws[threadIdx.x] = g_W[256 + (threadIdx.x & 15)*16 + (threadIdx.x >> 4)];
    __syncthreads();

    int warp = (blockIdx.x*blockDim.x + threadIdx.x) >> 5;
    int lane = threadIdx.x & 31;
    if (warp >= NN) return;
    int node = warp;
    int slot = lane >> 2;
    int cg   = lane & 3;
    int beg = g_rowptr[node], end = g_rowptr[node + 1];
    const uint2* xwh = (const uint2*)g_xwh;
    float di = g_dinv[node];

    float4 acc;
    if (slot == 0){
        float4 v = h4f(xwh[(size_t)node*4 + cg]);
        acc = make_float4(v.x*di, v.y*di, v.z*di, v.w*di);
    } else {
        acc = make_float4(0.f, 0.f, 0.f, 0.f);
    }

    int j = beg + slot;
    for (; j + 8 < end; j += 16){
        int s0 = g_csr[j];
        int s1 = g_csr[j + 8];
        float ds0 = g_dinv[s0];
        float ds1 = g_dinv[s1];
        float4 v0 = h4f(xwh[(size_t)s0*4 + cg]);
        float4 v1 = h4f(xwh[(size_t)s1*4 + cg]);
        acc.x = fmaf(v0.x, ds0, acc.x); acc.x = fmaf(v1.x, ds1, acc.x);
        acc.y = fmaf(v0.y, ds0, acc.y); acc.y = fmaf(v1.y, ds1, acc.y);
        acc.z = fmaf(v0.z, ds0, acc.z); acc.z = fmaf(v1.z, ds1, acc.z);
        acc.w = fmaf(v0.w, ds0, acc.w); acc.w = fmaf(v1.w, ds1, acc.w);
    }
    if (j < end){
        int s = g_csr[j];
        float ds = g_dinv[s];
        float4 v = h4f(xwh[(size_t)s*4 + cg]);
        acc.x = fmaf(v.x, ds, acc.x);
        acc.y = fmaf(v.y, ds, acc.y);
        acc.z = fmaf(v.z, ds, acc.z);
        acc.w = fmaf(v.w, ds, acc.w);
    }
#pragma unroll
    for (int off = 4; off < 32; off <<= 1){
        acc.x += __shfl_xor_sync(0xffffffff, acc.x, off);
        acc.y += __shfl_xor_sync(0xffffffff, acc.y, off);
        acc.z += __shfl_xor_sync(0xffffffff, acc.z, off);
        acc.w += __shfl_xor_sync(0xffffffff, acc.w, off);
    }
    const float* bp = gcnb + cg*4;
    float4 r;
    r.x = lrelu(di*acc.x + bp[0]);
    r.y = lrelu(di*acc.y + bp[1]);
    r.z = lrelu(di*acc.z + bp[2]);
    r.w = lrelu(di*acc.w + bp[3]);

    float hv[16];
    int qb = lane & ~3;
#pragma unroll
    for (int c = 0; c < 4; c++){
        int src = qb + c;
        hv[c*4+0] = __shfl_sync(0xffffffff, r.x, src);
        hv[c*4+1] = __shfl_sync(0xffffffff, r.y, src);
        hv[c*4+2] = __shfl_sync(0xffffffff, r.z, src);
        hv[c*4+3] = __shfl_sync(0xffffffff, r.w, src);
    }
    if (lane < 16){
        float a = 0.f;
#pragma unroll
        for (int i = 0; i < 16; i++) a += hv[i]*Ws[i*16 + lane];
        g_hh[(size_t)node*16 + lane] = __float2half(a * di);
    }
}

// ---------------- gather layer 1 + fused post heads ---------------------------------
__global__ void __launch_bounds__(256)
k_gather2(const float* __restrict__ gcnb,
          const float* __restrict__ po1W, const float* __restrict__ po1b,
          const float* __restrict__ poaW, const float* __restrict__ poab,
          float* __restrict__ out, int out_size){
    int warp = (blockIdx.x*blockDim.x + threadIdx.x) >> 5;
    int lane = threadIdx.x & 31;
    if (warp >= NN) return;
    int node = warp;
    int slot = lane >> 2;
    int cg   = lane & 3;
    int beg = g_rowptr[node], end = g_rowptr[node + 1];
    const uint2* xwh = (const uint2*)g_hh;

    float4 acc;
    if (slot == 0) acc = h4f(xwh[(size_t)node*4 + cg]);
    else           acc = make_float4(0.f, 0.f, 0.f, 0.f);

    int j = beg + slot;
    for (; j + 8 < end; j += 16){
        int s0 = g_csr[j];
        int s1 = g_csr[j + 8];
        float4 v0 = h4f(xwh[(size_t)s0*4 + cg]);
        float4 v1 = h4f(xwh[(size_t)s1*4 + cg]);
        acc.x += v0.x + v1.x;
        acc.y += v0.y + v1.y;
        acc.z += v0.z + v1.z;
        acc.w += v0.w + v1.w;
    }
    if (j < end){
        int s = g_csr[j];
        float4 v = h4f(xwh[(size_t)s*4 + cg]);
        acc.x += v.x; acc.y += v.y; acc.z += v.z; acc.w += v.w;
    }
#pragma unroll
    for (int off = 4; off < 32; off <<= 1){
        acc.x += __shfl_xor_sync(0xffffffff, acc.x, off);
        acc.y += __shfl_xor_sync(0xffffffff, acc.y, off);
        acc.z += __shfl_xor_sync(0xffffffff, acc.z, off);
        acc.w += __shfl_xor_sync(0xffffffff, acc.w, off);
    }
    if (lane < 4){
        float di = g_dinv[node];
        const float* bp = gcnb + 16 + cg*4;
        float4 r;
        r.x = lrelu(di*acc.x + bp[0]);
        r.y = lrelu(di*acc.y + bp[1]);
        r.z = lrelu(di*acc.z + bp[2]);
        r.w = lrelu(di*acc.w + bp[3]);
        if (out_size >= 18*NN)
            ((float4*)(out + 2*NN))[(size_t)node*4 + cg] = r;
        int c0 = cg*4;
        float sp = r.x*(po1W[c0+0] + po1W[16+c0+0])
                 + r.y*(po1W[c0+1] + po1W[16+c0+1])
                 + r.z*(po1W[c0+2] + po1W[16+c0+2])
                 + r.w*(po1W[c0+3] + po1W[16+c0+3]);
        float ap = r.x*poaW[c0+0] + r.y*poaW[c0+1]
                 + r.z*poaW[c0+2] + r.w*poaW[c0+3];
        unsigned qm = 0xFu << ((lane >> 2) << 2);
        sp += __shfl_xor_sync(qm, sp, 1); sp += __shfl_xor_sync(qm, sp, 2);
        ap += __shfl_xor_sync(qm, ap, 1); ap += __shfl_xor_sync(qm, ap, 2);
        if (cg == 0){
            out[node] = sp + po1b[0] + po1b[1];
            if (out_size >= 2*NN) out[NN + node] = ap + poab[0];
        }
    }
}

// ---------------- launch --------------------------------------------------------------
extern "C" void kernel_launch(void* const* d_in, const int* in_sizes, int n_in,
                              void* d_out, int out_size){
    const float* x    = (const float*)d_in[0];
    const int*   ei32 = (const int*)d_in[1];
    const float* p1W  = (const float*)d_in[2];
    const float* p1b  = (const float*)d_in[3];
    const float* p2W  = (const float*)d_in[4];
    const float* p2b  = (const float*)d_in[5];
    const float* bih  = (const float*)d_in[6];
    const float* bhh  = (const float*)d_in[7];
    const float* wtW  = (const float*)d_in[8];
    const float* wtb  = (const float*)d_in[9];
    const float* gcnb = (const float*)d_in[10];
    const float* po1W = (const float*)d_in[11];
    const float* po1b = (const float*)d_in[12];
    const float* poaW = (const float*)d_in[13];
    const float* poab = (const float*)d_in[14];
    float* out = (float*)d_out;

    cudaFuncSetAttribute(k_pre, cudaFuncAttributeMaxDynamicSharedMemorySize,
                         PRE_SMEM_BYTES);

    const int NB_N = (NN + 255)/256;
    const int NB_E2 = (NE/2 + 255)/256;
    const int NB_SCAN = (NN + 4095)/4096;   // 25
    const int NB_G = (NN*32 + 255)/256;     // warp per node
    const int NB_I = 2 + (NN + 511)/512;

    cudaStream_t s2 = 0;
    cudaEvent_t  evA = 0, evB = 0;
    bool fork = (cudaStreamCreateWithFlags(&s2, cudaStreamNonBlocking) == cudaSuccess);
    if (fork) fork = (cudaEventCreateWithFlags(&evA, cudaEventDisableTiming) == cudaSuccess);
    if (fork) fork = (cudaEventCreateWithFlags(&evB, cudaEventDisableTiming) == cudaSuccess);

    k_init<<<NB_I, 512>>>(ei32, bih, bhh, wtW, wtb);

    if (fork){
        cudaEventRecord(evA, 0);
        cudaStreamWaitEvent(s2, evA, 0);
        k_edges<<<NB_E2, 256, 0, s2>>>(ei32);
        k_scan1<<<NB_SCAN, 256, 0, s2>>>();
        k_scan3<<<NB_N, 256, 0, s2>>>();
        k_fill <<<NB_E2, 256, 0, s2>>>(ei32);
        cudaEventRecord(evB, s2);
        k_pre  <<<148, 512, PRE_SMEM_BYTES>>>(x, p1W, p1b, p2W, p2b);
        cudaStreamWaitEvent(0, evB, 0);
    } else {
        k_edges<<<NB_E2, 256>>>(ei32);
        k_scan1<<<NB_SCAN, 256>>>();
        k_scan3<<<NB_N, 256>>>();
        k_fill <<<NB_E2, 256>>>(ei32);
        k_pre  <<<148, 512, PRE_SMEM_BYTES>>>(x, p1W, p1b, p2W, p2b);
    }

    k_gather0<<<NB_G, 256>>>(gcnb);
    k_gather2<<<NB_G, 256>>>(gcnb, po1W, po1b, poaW, poab, out, out_size);
}